// round 12
// baseline (speedup 1.0000x reference)
#include <cuda_runtime.h>
#include <cuda_fp16.h>
#include <math.h>
#include <stdint.h>

#define MAXN 100000
#define MAXE 800000
#define H 128
#define NPAD (MAXN + 128)

// ---------------- device scratch ----------------
__device__ float g_hA[(size_t)MAXN * H];
__device__ float g_hB[(size_t)MAXN * H];
__device__ uint32_t g_hAh[(size_t)NPAD * 64];   // half2 frag-major mirrors
__device__ uint32_t g_hBh[(size_t)NPAD * 64];
__device__ uint32_t g_ngh[(size_t)NPAD * 64];
__device__ uint32_t g_Wh[(size_t)16 * 8704];    // frag-major weight panels (stride 68 per cb)
__device__ int   g_indeg[MAXN];
__device__ int   g_outdeg[MAXN];
__device__ int   g_cursor[MAXN];
__device__ int   g_off[MAXN];
__device__ int   g_csr[MAXE];
__device__ int   g_bsum[128];
__device__ float g_hp[MAXN];
__device__ float g_invdeg[MAXN];
__device__ float g_scores[MAXN];
__device__ float g_emb[H];
__device__ float g_sumexp;
__device__ unsigned g_maxbits;

__device__ __forceinline__ float neg_inf() { return __int_as_float(0xff800000); }
__device__ __forceinline__ unsigned encf(float f) {
    unsigned u = __float_as_uint(f);
    return (u & 0x80000000u) ? ~u : (u | 0x80000000u);
}
__device__ __forceinline__ float decf(unsigned u) {
    return (u & 0x80000000u) ? __uint_as_float(u ^ 0x80000000u) : __uint_as_float(~u);
}

// ---------------- fp16 helpers ----------------
__device__ __forceinline__ uint32_t f2h2(float a, float b) {
    __half2 h = __floats2half2_rn(a, b);
    return *(uint32_t*)&h;
}
__device__ __forceinline__ float2 h2f2(uint32_t u) {
    __half2 h = *(__half2*)&u;
    return __half22float2(h);
}
__device__ __forceinline__ void mma16816(float* c, uint32_t a0, uint32_t a1, uint32_t a2, uint32_t a3,
                                         uint32_t b0, uint32_t b1) {
    asm volatile("mma.sync.aligned.m16n8k16.row.col.f32.f16.f16.f32 "
                 "{%0,%1,%2,%3}, {%4,%5,%6,%7}, {%8,%9}, {%0,%1,%2,%3};"
                 : "+f"(c[0]), "+f"(c[1]), "+f"(c[2]), "+f"(c[3])
                 : "r"(a0), "r"(a1), "r"(a2), "r"(a3), "r"(b0), "r"(b1));
}
__device__ __forceinline__ uint32_t smem_u32(const void* p) {
    uint32_t a;
    asm("{ .reg .u64 t; cvta.to.shared.u64 t, %1; cvt.u32.u64 %0, t; }" : "=r"(a) : "l"(p));
    return a;
}
#define CP_COMMIT() asm volatile("cp.async.commit_group;" ::: "memory")
#define CP_WAIT0()  asm volatile("cp.async.wait_group 0;" ::: "memory")

// frag-major offset within a 64-u32 row/cb: kp -> kg*32 + tq*8 + ksub*2 + j
__device__ __forceinline__ int fragoff(int kp) {
    int tq = kp & 3, j = (kp >> 2) & 1, ks = kp >> 3;
    return (ks >> 2) * 32 + tq * 8 + (ks & 3) * 2 + j;
}
// output-column-pair -> frag-major slot (verified inverse of fragoff for kp = cb>>1)
__device__ __forceinline__ int fslot(int warpN, int nt, int tq) {
    return warpN * 32 + tq * 8 + ((nt >> 1) << 1) + (nt & 1);
}

// A tile: 128 rows x 64 u32 frag-major, stride 68.  W panel: 128 cb x 64 u32 frag-major, stride 68.
#define AP_STRIDE 68
#define SZ_AP (128 * AP_STRIDE)      // 8704 u32
#define PANEL_U32 8704
#define PANEL_LINES 2176
#define GSMEM_BYTES ((SZ_AP + PANEL_U32 + 128) * 4)
#define SSMEM_BYTES ((SZ_AP + PANEL_U32 + 512) * 4)
// tc_layer (multi-tile): Acur | Am | W0..W3 | consts | lnbuf
#define L_OFF_AM   SZ_AP
#define L_OFF_W0   (2 * SZ_AP)
#define L_OFF_SC   (2 * SZ_AP + 4 * PANEL_U32)
#define LSMEM_BYTES ((2 * SZ_AP + 4 * PANEL_U32 + 640 + 512) * 4)

// ---------------- loaders (512-thread CTAs) ----------------
// fp32 A rows -> frag-major half tile (input projection staging)
__device__ __forceinline__ void load_a_f32(const float4* __restrict__ G, int r0, int n, uint32_t* sm) {
    int t = threadIdx.x;
#pragma unroll
    for (int i = 0; i < 8; i++) {
        int g = t + i * 512;
        int row = g >> 5, c4 = g & 31;
        float4 v = make_float4(0.f, 0.f, 0.f, 0.f);
        if (r0 + row < n) v = G[(size_t)(r0 + row) * 32 + c4];
        sm[row * AP_STRIDE + fragoff(2 * c4)]     = f2h2(v.x, v.y);
        sm[row * AP_STRIDE + fragoff(2 * c4 + 1)] = f2h2(v.z, v.w);
    }
}
// async copy of frag-major A tile rows (layout-agnostic 16B lines)
__device__ __forceinline__ void copy_a_async(const uint32_t* __restrict__ src, int r0, int n, uint32_t dstb) {
    int t = threadIdx.x;
#pragma unroll
    for (int i = 0; i < 4; i++) {
        int g = t + i * 512;
        int row = g >> 4, q = g & 15;
        uint32_t dst = dstb + (uint32_t)(row * AP_STRIDE + q * 4) * 4u;
        const uint32_t* s = src + (size_t)(r0 + row) * 64 + q * 4;
        int sz = (r0 + row < n) ? 16 : 0;
        asm volatile("cp.async.cg.shared.global [%0], [%1], 16, %2;" :: "r"(dst), "l"(s), "r"(sz));
    }
}
// async copy of frag-major W panel: 2176 x 16B lines
__device__ __forceinline__ void copy_w_async(const uint32_t* __restrict__ src, uint32_t dstb) {
    int t = threadIdx.x;
#pragma unroll
    for (int i = 0; i < 5; i++) {
        int line = t + i * 512;
        if (line < PANEL_LINES) {
            uint32_t dst = dstb + (uint32_t)line * 16u;
            asm volatile("cp.async.cg.shared.global [%0], [%1], 16;" :: "r"(dst), "l"(src + line * 4));
        }
    }
}

// warp-tile MMA, kg-split for register economy. acc[8][4]; rows rb+gid / rb+gid+8.
__device__ __forceinline__ void mma_pass(const uint32_t* AP, int rb, const uint32_t* WB,
                                         int warpN, int gid, int tq, float acc[8][4]) {
    const uint32_t* r0p = AP + (rb + gid) * AP_STRIDE + tq * 8;
    const uint32_t* r8p = AP + (rb + gid + 8) * AP_STRIDE + tq * 8;
#pragma unroll
    for (int kg = 0; kg < 2; kg++) {
        uint32_t a0[8], a8[8];
        *(uint4*)(a0)     = *(const uint4*)(r0p + kg * 32);
        *(uint4*)(a0 + 4) = *(const uint4*)(r0p + kg * 32 + 4);
        *(uint4*)(a8)     = *(const uint4*)(r8p + kg * 32);
        *(uint4*)(a8 + 4) = *(const uint4*)(r8p + kg * 32 + 4);
#pragma unroll
        for (int nt = 0; nt < 8; nt++) {
            int cb = warpN * 64 + nt * 8 + gid;
            const uint32_t* q = WB + cb * AP_STRIDE + kg * 32 + tq * 8;
            uint32_t b[8];
            *(uint4*)(b)     = *(const uint4*)(q);
            *(uint4*)(b + 4) = *(const uint4*)(q + 4);
#pragma unroll
            for (int ks = 0; ks < 4; ks++)
                mma16816(acc[nt], a0[2 * ks], a8[2 * ks], a0[2 * ks + 1], a8[2 * ks + 1],
                         b[2 * ks], b[2 * ks + 1]);
        }
    }
}

// ---------------- weight preconversion (frag-major panels) ----------------
__global__ void wconv_kernel(const float* __restrict__ W_in, const float* __restrict__ Ws,
                             const float* __restrict__ Wn, const float* __restrict__ Wg,
                             const float* __restrict__ W_att, int L) {
    int idx = blockIdx.x * blockDim.x + threadIdx.x;
    int total = (4 * L + 2) * PANEL_U32;
    if (idx >= total) return;
    int p = idx / PANEL_U32;
    int r = idx % PANEL_U32;
    int cb = r / AP_STRIDE, o = r % AP_STRIDE;
    if (o >= 64) { g_Wh[idx] = 0u; return; }
    int kg = o >> 5, tq = (o >> 3) & 3, ksub = (o >> 1) & 3, j = o & 1;
    int kp = (kg * 4 + ksub) * 8 + tq + 4 * j;
    const float* src;
    if (p == 0) src = W_in;
    else if (p <= L) src = Ws + (size_t)(p - 1) * H * H;
    else if (p <= 2 * L) src = Wn + (size_t)(p - 1 - L) * H * H;
    else if (p <= 3 * L) src = Wg + (size_t)(p - 1 - 2 * L) * 2 * H * H;
    else if (p <= 4 * L) src = Wg + (size_t)(p - 1 - 3 * L) * 2 * H * H + (size_t)H * H;
    else src = W_att;
    g_Wh[idx] = f2h2(src[(size_t)(2 * kp) * H + cb], src[(size_t)(2 * kp + 1) * H + cb]);
}

// ---------------- GEMM (input projection): C = A@W + bias, + frag-major half mirror ----------------
__global__ __launch_bounds__(512, 2) void tc_gemm(
    const float* __restrict__ A, const uint32_t* __restrict__ Wp,
    const float* __restrict__ bias, float* __restrict__ C, uint32_t* __restrict__ Ch, int n)
{
    extern __shared__ uint32_t smem[];
    uint32_t* AP = smem;
    uint32_t* WB = smem + SZ_AP;
    float* sb = (float*)(smem + SZ_AP + PANEL_U32);
    uint32_t sbase = smem_u32(smem);

    int tid = threadIdx.x, wid = tid >> 5, lane = tid & 31;
    int warpM = wid >> 1, warpN = wid & 1, gid = lane >> 2, tq = lane & 3;
    int r0 = blockIdx.x * 128;
    int rb = warpM * 16;

    copy_w_async(Wp, sbase + SZ_AP * 4);
    CP_COMMIT();
    load_a_f32((const float4*)A, r0, n, AP);
    if (tid < 128) sb[tid] = bias[tid];
    CP_WAIT0();
    __syncthreads();

    float acc[8][4];
#pragma unroll
    for (int nt = 0; nt < 8; nt++)
#pragma unroll
        for (int j = 0; j < 4; j++) acc[nt][j] = 0.f;

    mma_pass(AP, rb, WB, warpN, gid, tq, acc);

#pragma unroll
    for (int p = 0; p < 2; p++) {
        int row = r0 + rb + p * 8 + gid;
        if (row >= n) continue;
#pragma unroll
        for (int nt = 0; nt < 8; nt++) {
            int cb = warpN * 64 + nt * 8 + 2 * tq;
            float2 o;
            o.x = acc[nt][2 * p + 0] + sb[cb];
            o.y = acc[nt][2 * p + 1] + sb[cb + 1];
            *(float2*)(C + (size_t)row * H + cb) = o;
            Ch[(size_t)row * 64 + fslot(warpN, nt, tq)] = f2h2(o.x, o.y);
        }
    }
}

// ---------------- multi-tile fused layer kernel (all 4 W panels resident) ----------------
__global__ __launch_bounds__(512) void tc_layer(
    const float* __restrict__ curf, const uint32_t* __restrict__ curh,
    const uint32_t* __restrict__ ngh,
    const uint32_t* __restrict__ Wsp, const uint32_t* __restrict__ Wnp,
    const uint32_t* __restrict__ WgAp, const uint32_t* __restrict__ WgBp,
    const float* __restrict__ bs, const float* __restrict__ bn, const float* __restrict__ bg,
    const float* __restrict__ coef,
    const float* __restrict__ gamma, const float* __restrict__ beta,
    float* __restrict__ Houtf, uint32_t* __restrict__ Houth, int n, int nTiles)
{
    extern __shared__ uint32_t smem[];
    uint32_t* Acur = smem;
    uint32_t* Am   = smem + L_OFF_AM;
    uint32_t* W0   = smem + L_OFF_W0;
    float* sc  = (float*)(smem + L_OFF_SC);
    float* lnb = sc + 640;
    uint32_t sbase = smem_u32(smem);

    int tid = threadIdx.x, wid = tid >> 5, lane = tid & 31;
    int warpM = wid >> 1, warpN = wid & 1, gid = lane >> 2, tq = lane & 3;
    int rb = warpM * 16;

    int t0 = blockIdx.x;
    if (t0 < nTiles) {
        copy_a_async(curh, t0 * 128, n, sbase);
        copy_a_async(ngh, t0 * 128, n, sbase + L_OFF_AM * 4);
    }
    copy_w_async(Wsp,  sbase + L_OFF_W0 * 4);
    copy_w_async(Wnp,  sbase + (L_OFF_W0 + PANEL_U32) * 4);
    copy_w_async(WgAp, sbase + (L_OFF_W0 + 2 * PANEL_U32) * 4);
    copy_w_async(WgBp, sbase + (L_OFF_W0 + 3 * PANEL_U32) * 4);
    CP_COMMIT();
    if (tid < 128) {
        sc[tid] = bs[tid]; sc[128 + tid] = bn[tid]; sc[256 + tid] = bg[tid];
        sc[384 + tid] = gamma[tid]; sc[512 + tid] = beta[tid];
    }
    CP_WAIT0();
    __syncthreads();

    for (int tile = t0; tile < nTiles; tile += gridDim.x) {
        int r0 = tile * 128;

        float acc1[8][4], acc2[8][4];
#pragma unroll
        for (int nt = 0; nt < 8; nt++)
#pragma unroll
            for (int j = 0; j < 4; j++) { acc1[nt][j] = 0.f; acc2[nt][j] = 0.f; }

        mma_pass(Acur, rb, W0, warpN, gid, tq, acc1);                   // cur@Ws
        mma_pass(Am,   rb, W0 + PANEL_U32, warpN, gid, tq, acc1);       // += neigh@Wn
        mma_pass(Acur, rb, W0 + 2 * PANEL_U32, warpN, gid, tq, acc2);   // cur@WgA
        __syncthreads();   // all warps finished reading Am(neigh)

        // m = acc1 + bs + cf*bn (exact fp32 in regs); write half m over Am (frag-major)
#pragma unroll
        for (int p = 0; p < 2; p++) {
            int lrow = rb + p * 8 + gid;
            int row = r0 + lrow;
            if (row >= n) continue;
            float cf = coef[row];
#pragma unroll
            for (int nt = 0; nt < 8; nt++) {
                int cb = warpN * 64 + nt * 8 + 2 * tq;
                float v0 = acc1[nt][2 * p + 0] + sc[cb + 0] + cf * sc[128 + cb + 0];
                float v1 = acc1[nt][2 * p + 1] + sc[cb + 1] + cf * sc[128 + cb + 1];
                acc1[nt][2 * p + 0] = v0;
                acc1[nt][2 * p + 1] = v1;
                Am[lrow * AP_STRIDE + fslot(warpN, nt, tq)] = f2h2(v0, v1);
            }
        }
        __syncthreads();   // m visible
        mma_pass(Am, rb, W0 + 3 * PANEL_U32, warpN, gid, tq, acc2);     // += m@WgB
        __syncthreads();   // all reads of Acur/Am complete

        int tnext = tile + gridDim.x;
        if (tnext < nTiles) {
            copy_a_async(curh, tnext * 128, n, sbase);
            copy_a_async(ngh, tnext * 128, n, sbase + L_OFF_AM * 4);
            CP_COMMIT();
        }

        // epilogue: gate + blend (exact fp32 h) + LN + ReLU
        float rsum[2] = {0.f, 0.f};
        float rsq[2] = {0.f, 0.f};
#pragma unroll
        for (int p = 0; p < 2; p++) {
            int row = r0 + rb + p * 8 + gid;
            if (row >= n) continue;
            const float* hrow = curf + (size_t)row * H;
#pragma unroll
            for (int nt = 0; nt < 8; nt++) {
                int cb = warpN * 64 + nt * 8 + 2 * tq;
                float2 hv = *(const float2*)(hrow + cb);
                float pre, g, v;
                pre = acc2[nt][2 * p + 0] + sc[256 + cb];
                g = 1.f / (1.f + expf(-pre));
                v = g * acc1[nt][2 * p + 0] + (1.f - g) * hv.x;
                acc1[nt][2 * p + 0] = v; rsum[p] += v; rsq[p] += v * v;
                pre = acc2[nt][2 * p + 1] + sc[256 + cb + 1];
                g = 1.f / (1.f + expf(-pre));
                v = g * acc1[nt][2 * p + 1] + (1.f - g) * hv.y;
                acc1[nt][2 * p + 1] = v; rsum[p] += v; rsq[p] += v * v;
            }
        }
#pragma unroll
        for (int p = 0; p < 2; p++) {
            rsum[p] += __shfl_xor_sync(0xffffffffu, rsum[p], 1);
            rsum[p] += __shfl_xor_sync(0xffffffffu, rsum[p], 2);
            rsq[p] += __shfl_xor_sync(0xffffffffu, rsq[p], 1);
            rsq[p] += __shfl_xor_sync(0xffffffffu, rsq[p], 2);
        }
        if (tq == 0) {
#pragma unroll
            for (int p = 0; p < 2; p++) {
                int lrow = rb + p * 8 + gid;
                lnb[lrow * 4 + warpN * 2 + 0] = rsum[p];
                lnb[lrow * 4 + warpN * 2 + 1] = rsq[p];
            }
        }
        __syncthreads();
#pragma unroll
        for (int p = 0; p < 2; p++) {
            int lrow = rb + p * 8 + gid;
            int row = r0 + lrow;
            if (row >= n) continue;
            float sum = lnb[lrow * 4 + 0] + lnb[lrow * 4 + 2];
            float sq  = lnb[lrow * 4 + 1] + lnb[lrow * 4 + 3];
            float mu = sum * (1.f / 128.f);
            float var = sq * (1.f / 128.f) - mu * mu;
            float rs = rsqrtf(var + 1e-5f);
            float* orow = Houtf + (size_t)row * H;
#pragma unroll
            for (int nt = 0; nt < 8; nt++) {
                int cb = warpN * 64 + nt * 8 + 2 * tq;
                float2 o;
                o.x = fmaxf(fmaf((acc1[nt][2 * p + 0] - mu) * rs, sc[384 + cb], sc[512 + cb]), 0.f);
                o.y = fmaxf(fmaf((acc1[nt][2 * p + 1] - mu) * rs, sc[384 + cb + 1], sc[512 + cb + 1]), 0.f);
                *(float2*)(orow + cb) = o;
                Houth[(size_t)row * 64 + fslot(warpN, nt, tq)] = f2h2(o.x, o.y);
            }
        }
        if (tnext < nTiles) CP_WAIT0();
        __syncthreads();
    }
}

// ---------------- fused attention score ----------------
__global__ __launch_bounds__(512, 2) void tc_score(
    const uint32_t* __restrict__ Ah, const uint32_t* __restrict__ Wp,
    const float* __restrict__ bias, const float* __restrict__ Wsc,
    const float* __restrict__ bsc, int n)
{
    extern __shared__ uint32_t smem[];
    uint32_t* AP = smem;
    uint32_t* WB = smem + SZ_AP;
    float* sb = (float*)(smem + SZ_AP + PANEL_U32);
    float* sw = sb + 128;
    float* lnb = sw + 128;
    uint32_t sbase = smem_u32(smem);

    int tid = threadIdx.x, wid = tid >> 5, lane = tid & 31;
    int warpM = wid >> 1, warpN = wid & 1, gid = lane >> 2, tq = lane & 3;
    int r0 = blockIdx.x * 128;
    int rb = warpM * 16;

    copy_a_async(Ah, r0, n, sbase);
    copy_w_async(Wp, sbase + SZ_AP * 4);
    if (tid < 128) sb[tid] = bias[tid];
    else if (tid < 256) sw[tid - 128] = Wsc[tid - 128];
    CP_COMMIT(); CP_WAIT0();
    __syncthreads();

    float acc[8][4];
#pragma unroll
    for (int nt = 0; nt < 8; nt++)
#pragma unroll
        for (int j = 0; j < 4; j++) acc[nt][j] = 0.f;

    mma_pass(AP, rb, WB, warpN, gid, tq, acc);

    float part[2] = {0.f, 0.f};
#pragma unroll
    for (int nt = 0; nt < 8; nt++) {
        int cb = warpN * 64 + nt * 8 + 2 * tq;
#pragma unroll
        for (int p = 0; p < 2; p++) {
            part[p] += tanhf(acc[nt][2 * p + 0] + sb[cb]) * sw[cb];
            part[p] += tanhf(acc[nt][2 * p + 1] + sb[cb + 1]) * sw[cb + 1];
        }
    }
#pragma unroll
    for (int p = 0; p < 2; p++) {
        part[p] += __shfl_xor_sync(0xffffffffu, part[p], 1);
        part[p] += __shfl_xor_sync(0xffffffffu, part[p], 2);
    }
    if (tq == 0) {
#pragma unroll
        for (int p = 0; p < 2; p++) {
            int lrow = rb + p * 8 + gid;
            lnb[lrow * 2 + warpN] = part[p];
        }
    }
    __syncthreads();
    if (warpN == 0 && tq == 0) {
#pragma unroll
        for (int p = 0; p < 2; p++) {
            int lrow = rb + p * 8 + gid;
            int row = r0 + lrow;
            if (row >= n) continue;
            float scv = lnb[lrow * 2 + 0] + lnb[lrow * 2 + 1] + bsc[0];
            bool sink = (g_outdeg[row] == 0);
            g_scores[row] = sink ? scv : neg_inf();
            if (sink) atomicMax(&g_maxbits, encf(scv));
        }
    }
}

// ---------------- graph prep ----------------
__global__ void zero_kernel(int n) {
    int i = blockIdx.x * blockDim.x + threadIdx.x;
    if (i < n) { g_indeg[i] = 0; g_outdeg[i] = 0; g_cursor[i] = 0; }
    if (i < H) g_emb[i] = 0.f;
    if (i == 0) { g_maxbits = encf(neg_inf()); g_sumexp = 0.f; }
}
__global__ void deg_kernel(const int* __restrict__ src, const int* __restrict__ dst, int e) {
    int i = blockIdx.x * blockDim.x + threadIdx.x;
    if (i < e) { atomicAdd(&g_indeg[dst[i]], 1); atomicAdd(&g_outdeg[src[i]], 1); }
}
__global__ void prep_kernel(int n) {
    int i = blockIdx.x * blockDim.x + threadIdx.x;
    if (i < n) {
        int d = g_indeg[i];
        g_hp[i] = d > 0 ? 1.f : 0.f;
        g_invdeg[i] = 1.f / (float)(d > 0 ? d : 1);
    }
}
__global__ void scan1_kernel(int n) {
    __shared__ int sm[1024];
    int t = threadIdx.x;
    int i = blockIdx.x * 1024 + t;
    int v = (i < n) ? g_indeg[i] : 0;
    sm[t] = v;
    __syncthreads();
    for (int off = 1; off < 1024; off <<= 1) {
        int x = (t >= off) ? sm[t - off] : 0;
        __syncthreads();
        sm[t] += x;
        __syncthreads();
    }
    if (i < n) g_off[i] = sm[t] - v;
    if (t == 1023) g_bsum[blockIdx.x] = sm[1023];
}
__global__ void scan2_kernel(int nb) {
    if (threadIdx.x == 0) {
        int c = 0;
        for (int i = 0; i < nb; i++) { int x = g_bsum[i]; g_bsum[i] = c; c += x; }
    }
}
__global__ void scan3_kernel(int n) {
    int i = blockIdx.x * blockDim.x + threadIdx.x;
    if (i < n) g_off[i] += g_bsum[i >> 10];
}
__global__ void fill_kernel(const int* __restrict__ src, const int* __restrict__ dst, int e) {
    int i = blockIdx.x * blockDim.x + threadIdx.x;
    if (i < e) {
        int d = dst[i];
        int p = g_off[d] + atomicAdd(&g_cursor[d], 1);
        g_csr[p] = src[i];
    }
}

// ---------------- neighbor mean (positional over frag-major mirror) ----------------
__global__ void neigh_kernel(const uint32_t* __restrict__ Hh, uint32_t* __restrict__ Ngh, int n) {
    int gw = (blockIdx.x * blockDim.x + threadIdx.x) >> 5;
    int lane = threadIdx.x & 31;
    if (gw >= n) return;
    int start = g_off[gw];
    int deg = g_indeg[gw];
    const uint2* H2 = (const uint2*)Hh;
    float4 acc = make_float4(0.f, 0.f, 0.f, 0.f);
    for (int base = 0; base < deg; base += 32) {
        int e = base + lane;
        int s = (e < deg) ? g_csr[start + e] : 0;
        int cnt = min(32, deg - base);
        for (int j = 0; j < cnt; j++) {
            int sj = __shfl_sync(0xffffffffu, s, j);
            uint2 v = H2[(size_t)sj * 32 + lane];
            float2 f0 = h2f2(v.x), f1 = h2f2(v.y);
            acc.x += f0.x; acc.y += f0.y; acc.z += f1.x; acc.w += f1.y;
        }
    }
    float iv = g_invdeg[gw];
    uint2 o;
    o.x = f2h2(acc.x * iv, acc.y * iv);
    o.y = f2h2(acc.z * iv, acc.w * iv);
    ((uint2*)Ngh)[(size_t)gw * 32 + lane] = o;
}

// ---------------- pooling ----------------
__global__ void pool2_kernel(const float* __restrict__ Hin, int n) {
    __shared__ float sb[8 * 128];
    __shared__ float se[8];
    int tid = threadIdx.x, w = tid >> 5, lane = tid & 31;
    int gw = (blockIdx.x * blockDim.x + tid) >> 5;
    int nw = (gridDim.x * blockDim.x) >> 5;
    float mx = decf(g_maxbits);
    const float4* H4 = (const float4*)Hin;
    float4 acc = make_float4(0.f, 0.f, 0.f, 0.f);
    float es = 0.f;
    for (int i = gw; i < n; i += nw) {
        float s = g_scores[i];
        if (s >= -1e30f) {
            float e = expf(s - mx);
            if (lane == 0) es += e;
            float4 hv = H4[(size_t)i * 32 + lane];
            acc.x += e * hv.x; acc.y += e * hv.y; acc.z += e * hv.z; acc.w += e * hv.w;
        }
    }
    *(float4*)&sb[w * 128 + lane * 4] = acc;
    if (lane == 0) se[w] = es;
    __syncthreads();
    if (tid < 128) {
        float t = 0.f;
#pragma unroll
        for (int j = 0; j < 8; j++) t += sb[j * 128 + tid];
        if (t != 0.f) atomicAdd(&g_emb[tid], t);
    }
    if (tid == 0) {
        float t = 0.f;
#pragma unroll
        for (int j = 0; j < 8; j++) t += se[j];
        if (t != 0.f) atomicAdd(&g_sumexp, t);
    }
}
__global__ void finish_kernel(float* __restrict__ gout) {
    int t = threadIdx.x;
    gout[t] = g_emb[t] / g_sumexp;
}

// ---------------- launch ----------------
extern "C" void kernel_launch(void* const* d_in, const int* in_sizes, int n_in,
                              void* d_out, int out_size)
{
    const float* node_feats = (const float*)d_in[0];
    const int*   src        = (const int*)d_in[1];
    const int*   dst        = (const int*)d_in[2];
    const float* W_in       = (const float*)d_in[3];
    const float* b_in       = (const float*)d_in[4];
    const float* Ws         = (const float*)d_in[5];
    const float* bs         = (const float*)d_in[6];
    const float* Wn         = (const float*)d_in[7];
    const float* bn         = (const float*)d_in[8];
    const float* Wg         = (const float*)d_in[9];
    const float* bg         = (const float*)d_in[10];
    const float* gamma      = (const float*)d_in[11];
    const float* beta       = (const float*)d_in[12];
    const float* W_att      = (const float*)d_in[13];
    const float* b_att      = (const float*)d_in[14];
    const float* W_score    = (const float*)d_in[15];
    const float* b_score    = (const float*)d_in[16];

    int n = in_sizes[0] / H;
    int e = in_sizes[1];
    int L = in_sizes[6] / H;

    float* out_h = (float*)d_out;
    float* out_g = out_h + (size_t)n * H;

    float *hA, *hB, *hp;
    uint32_t *hAh, *hBh, *ngh, *Wh;
    cudaGetSymbolAddress((void**)&hA, g_hA);
    cudaGetSymbolAddress((void**)&hB, g_hB);
    cudaGetSymbolAddress((void**)&hAh, g_hAh);
    cudaGetSymbolAddress((void**)&hBh, g_hBh);
    cudaGetSymbolAddress((void**)&ngh, g_ngh);
    cudaGetSymbolAddress((void**)&hp, g_hp);
    cudaGetSymbolAddress((void**)&Wh, g_Wh);

    cudaFuncSetAttribute(tc_gemm,  cudaFuncAttributeMaxDynamicSharedMemorySize, GSMEM_BYTES);
    cudaFuncSetAttribute(tc_score, cudaFuncAttributeMaxDynamicSharedMemorySize, SSMEM_BYTES);
    cudaFuncSetAttribute(tc_layer, cudaFuncAttributeMaxDynamicSharedMemorySize, LSMEM_BYTES);

    int nbN = (n + 255) / 256;
    int nbE = (e + 255) / 256;
    int nbT = (n + 127) / 128;
    int nbW = (n + 7) / 8;
    int nbS = (n + 1023) / 1024;
    int wtotal = (4 * L + 2) * PANEL_U32;

    // launch order keeps tc_gemm 4th (ncu capture slot)
    wconv_kernel<<<(wtotal + 255) / 256, 256>>>(W_in, Ws, Wn, Wg, W_att, L);
    zero_kernel<<<nbN, 256>>>(n);
    deg_kernel<<<nbE, 256>>>(src, dst, e);
    tc_gemm<<<nbT, 512, GSMEM_BYTES>>>(node_feats, Wh, b_in, hA, hAh, n);
    prep_kernel<<<nbN, 256>>>(n);
    scan1_kernel<<<nbS, 1024>>>(n);
    scan2_kernel<<<1, 32>>>(nbS);
    scan3_kernel<<<nbN, 256>>>(n);
    fill_kernel<<<nbE, 256>>>(src, dst, e);

    float* cur = hA;       uint32_t* curh = hAh;
    float* other = hB;     uint32_t* otherh = hBh;
    for (int i = 0; i < L; i++) {
        const uint32_t* Wsp  = Wh + (size_t)(1 + i) * PANEL_U32;
        const uint32_t* Wnp  = Wh + (size_t)(1 + L + i) * PANEL_U32;
        const uint32_t* WgAp = Wh + (size_t)(1 + 2 * L + i) * PANEL_U32;
        const uint32_t* WgBp = Wh + (size_t)(1 + 3 * L + i) * PANEL_U32;
        const float* bs_i = bs + (size_t)i * H;
        const float* bn_i = bn + (size_t)i * H;
        const float* bg_i = bg + (size_t)i * H;
        const float* ga_i = gamma + (size_t)i * H;
        const float* be_i = beta + (size_t)i * H;

        neigh_kernel<<<nbW, 256>>>(curh, ngh, n);
        float* outp = (i == L - 1) ? out_h : other;
        tc_layer<<<148, 512, LSMEM_BYTES>>>(cur, curh, ngh, Wsp, Wnp, WgAp, WgBp,
                                            bs_i, bn_i, bg_i, hp, ga_i, be_i,
                                            outp, otherh, n, nbT);
        other = cur;
        cur = outp;
        uint32_t* th = curh; curh = otherh; otherh = th;
    }

    tc_score<<<nbT, 512, SSMEM_BYTES>>>(curh, Wh + (size_t)(4 * L + 1) * PANEL_U32,
                                        b_att, W_score, b_score, n);
    pool2_kernel<<<64, 256>>>(cur, n);
    finish_kernel<<<1, 128>>>(out_g);
}

// round 13
// speedup vs baseline: 1.3152x; 1.3152x over previous
#include <cuda_runtime.h>
#include <cuda_fp16.h>
#include <math.h>
#include <stdint.h>

#define MAXN 100000
#define MAXE 800000
#define H 128
#define NPAD (MAXN + 128)

// ---------------- device scratch ----------------
__device__ float g_hA[(size_t)MAXN * H];
__device__ uint32_t g_hAh[(size_t)NPAD * 64];   // half2 k-pair mirrors
__device__ uint32_t g_hBh[(size_t)NPAD * 64];
__device__ uint32_t g_ngh[(size_t)NPAD * 64];
__device__ uint4 g_Wh4[16 * 2048];              // preconverted weight panels (half2 kpair)
__device__ int   g_indeg[MAXN];
__device__ int   g_outdeg[MAXN];
__device__ int   g_cursor[MAXN];
__device__ int   g_off[MAXN];
__device__ int   g_csr[MAXE];
__device__ int   g_bsum[128];
__device__ float g_hp[MAXN];
__device__ float g_invdeg[MAXN];
__device__ float g_scores[MAXN];
__device__ float g_emb[H];
__device__ float g_sumexp;
__device__ unsigned g_maxbits;

__device__ __forceinline__ float neg_inf() { return __int_as_float(0xff800000); }
__device__ __forceinline__ unsigned encf(float f) {
    unsigned u = __float_as_uint(f);
    return (u & 0x80000000u) ? ~u : (u | 0x80000000u);
}
__device__ __forceinline__ float decf(unsigned u) {
    return (u & 0x80000000u) ? __uint_as_float(u ^ 0x80000000u) : __uint_as_float(~u);
}

// ---------------- fp16 helpers ----------------
__device__ __forceinline__ uint32_t f2h2(float a, float b) {
    __half2 h = __floats2half2_rn(a, b);
    return *(uint32_t*)&h;
}
__device__ __forceinline__ float2 h2f2(uint32_t u) {
    __half2 h = *(__half2*)&u;
    return __half22float2(h);
}
__device__ __forceinline__ void mma16816(float* c, uint32_t a0, uint32_t a1, uint32_t a2, uint32_t a3,
                                         uint32_t b0, uint32_t b1) {
    asm volatile("mma.sync.aligned.m16n8k16.row.col.f32.f16.f16.f32 "
                 "{%0,%1,%2,%3}, {%4,%5,%6,%7}, {%8,%9}, {%0,%1,%2,%3};"
                 : "+f"(c[0]), "+f"(c[1]), "+f"(c[2]), "+f"(c[3])
                 : "r"(a0), "r"(a1), "r"(a2), "r"(a3), "r"(b0), "r"(b1));
}
__device__ __forceinline__ uint32_t smem_u32(const void* p) {
    uint32_t a;
    asm("{ .reg .u64 t; cvta.to.shared.u64 t, %1; cvt.u32.u64 %0, t; }" : "=r"(a) : "l"(p));
    return a;
}
#define CP_COMMIT() asm volatile("cp.async.commit_group;" ::: "memory")
#define CP_WAIT0()  asm volatile("cp.async.wait_group 0;" ::: "memory")

// A tile: 128 rows x 64 half2, stride 68 u32.  W tile: 64 kp-rows x 128 half2, stride 136 u32.
#define AP_STRIDE 68
#define WP_STRIDE 136
#define SZ_AP (128 * AP_STRIDE)     // 8704 u32
#define SZ_WP (64 * WP_STRIDE)      // 8704 u32
#define GSMEM_BYTES ((SZ_AP + SZ_WP + 128) * 4)
#define SSMEM_BYTES ((SZ_AP + SZ_WP + 512) * 4)
// tc_layer (multi-tile): Acur | Am | W0..W3 | consts | lnbuf
#define L_OFF_AM   SZ_AP
#define L_OFF_W0   (2 * SZ_AP)
#define L_OFF_SC   (2 * SZ_AP + 4 * SZ_WP)
#define LSMEM_BYTES ((2 * SZ_AP + 4 * SZ_WP + 640 + 512) * 4)

// ---------------- tile loaders (512-thread CTAs) ----------------
__device__ __forceinline__ void load_a_f32(const float4* __restrict__ G, int r0, int n, uint32_t* sm) {
    int t = threadIdx.x;
#pragma unroll
    for (int i = 0; i < 8; i++) {
        int g = t + i * 512;
        int row = g >> 5, c4 = g & 31;
        float4 v = make_float4(0.f, 0.f, 0.f, 0.f);
        if (r0 + row < n) v = G[(size_t)(r0 + row) * 32 + c4];
        uint2 w;
        w.x = f2h2(v.x, v.y);
        w.y = f2h2(v.z, v.w);
        *(uint2*)(sm + row * AP_STRIDE + c4 * 2) = w;
    }
}
__device__ __forceinline__ void copy_a_async(const uint32_t* __restrict__ src, int r0, int n, uint32_t dstb) {
    int t = threadIdx.x;
#pragma unroll
    for (int i = 0; i < 4; i++) {
        int g = t + i * 512;
        int row = g >> 4, q = g & 15;
        uint32_t dst = dstb + (uint32_t)(row * AP_STRIDE + q * 4) * 4u;
        const uint32_t* s = src + (size_t)(r0 + row) * 64 + q * 4;
        int sz = (r0 + row < n) ? 16 : 0;
        asm volatile("cp.async.cg.shared.global [%0], [%1], 16, %2;" :: "r"(dst), "l"(s), "r"(sz));
    }
}
__device__ __forceinline__ void copy_w_async(const uint4* __restrict__ src, uint32_t dstb) {
    int t = threadIdx.x;
#pragma unroll
    for (int i = 0; i < 4; i++) {
        int g = t + i * 512;
        int kp = g >> 5, c4 = g & 31;
        uint32_t dst = dstb + (uint32_t)(kp * WP_STRIDE + c4 * 4) * 4u;
        asm volatile("cp.async.cg.shared.global [%0], [%1], 16;" :: "r"(dst), "l"(src + kp * 32 + c4));
    }
}

// warp-tile MMA: 16 warps, each 16 rows x 64 cols -> acc[8][4]
__device__ __forceinline__ void mma_tile(const uint32_t* AP, const uint32_t* WP,
                                         float acc[8][4], int rb, int warpN,
                                         int gid, int tq) {
#pragma unroll
    for (int ks = 0; ks < 8; ks++) {
        int kp0 = ks * 8;
        uint32_t a0 = AP[(rb + gid) * AP_STRIDE + kp0 + tq];
        uint32_t a1 = AP[(rb + gid + 8) * AP_STRIDE + kp0 + tq];
        uint32_t a2 = AP[(rb + gid) * AP_STRIDE + kp0 + tq + 4];
        uint32_t a3 = AP[(rb + gid + 8) * AP_STRIDE + kp0 + tq + 4];
#pragma unroll
        for (int nt = 0; nt < 8; nt++) {
            int cb = warpN * 64 + nt * 8 + gid;
            uint32_t b0 = WP[(kp0 + tq) * WP_STRIDE + cb];
            uint32_t b1 = WP[(kp0 + tq + 4) * WP_STRIDE + cb];
            mma16816(acc[nt], a0, a1, a2, a3, b0, b1);
        }
    }
}

// dual-pass MMA: shared A fragments feed two weight panels (acc1 += A@W1, acc2 += A@W2)
__device__ __forceinline__ void mma_tile2(const uint32_t* AP, const uint32_t* W1, const uint32_t* W2,
                                          float acc1[8][4], float acc2[8][4], int rb, int warpN,
                                          int gid, int tq) {
#pragma unroll
    for (int ks = 0; ks < 8; ks++) {
        int kp0 = ks * 8;
        uint32_t a0 = AP[(rb + gid) * AP_STRIDE + kp0 + tq];
        uint32_t a1 = AP[(rb + gid + 8) * AP_STRIDE + kp0 + tq];
        uint32_t a2 = AP[(rb + gid) * AP_STRIDE + kp0 + tq + 4];
        uint32_t a3 = AP[(rb + gid + 8) * AP_STRIDE + kp0 + tq + 4];
#pragma unroll
        for (int nt = 0; nt < 8; nt++) {
            int cb = warpN * 64 + nt * 8 + gid;
            uint32_t b0 = W1[(kp0 + tq) * WP_STRIDE + cb];
            uint32_t b1 = W1[(kp0 + tq + 4) * WP_STRIDE + cb];
            mma16816(acc1[nt], a0, a1, a2, a3, b0, b1);
            uint32_t c0 = W2[(kp0 + tq) * WP_STRIDE + cb];
            uint32_t c1 = W2[(kp0 + tq + 4) * WP_STRIDE + cb];
            mma16816(acc2[nt], a0, a1, a2, a3, c0, c1);
        }
    }
}

// ---------------- weight preconversion ----------------
__global__ void wconv_kernel(const float* __restrict__ W_in, const float* __restrict__ Ws,
                             const float* __restrict__ Wn, const float* __restrict__ Wg,
                             const float* __restrict__ W_att, int L) {
    int idx = blockIdx.x * blockDim.x + threadIdx.x;
    int total = (4 * L + 2) * 8192;
    if (idx >= total) return;
    int p = idx >> 13;
    int j = idx & 8191;
    int kp = j >> 7, nn = j & 127;
    const float* src;
    if (p == 0) src = W_in;
    else if (p <= L) src = Ws + (size_t)(p - 1) * H * H;
    else if (p <= 2 * L) src = Wn + (size_t)(p - 1 - L) * H * H;
    else if (p <= 3 * L) src = Wg + (size_t)(p - 1 - 2 * L) * 2 * H * H;
    else if (p <= 4 * L) src = Wg + (size_t)(p - 1 - 3 * L) * 2 * H * H + (size_t)H * H;
    else src = W_att;
    ((uint32_t*)g_Wh4)[idx] = f2h2(src[(size_t)(2 * kp) * H + nn], src[(size_t)(2 * kp + 1) * H + nn]);
}

// ---------------- GEMM (input projection): C = A@W + bias, + half mirror ----------------
__global__ __launch_bounds__(512) void tc_gemm(
    const float* __restrict__ A, const uint4* __restrict__ Wp,
    const float* __restrict__ bias, float* __restrict__ C, uint32_t* __restrict__ Ch, int n)
{
    extern __shared__ uint32_t smem[];
    uint32_t* AP = smem;
    uint32_t* WP = smem + SZ_AP;
    float* sb = (float*)(smem + SZ_AP + SZ_WP);
    uint32_t sbase = smem_u32(smem);

    int tid = threadIdx.x, wid = tid >> 5, lane = tid & 31;
    int warpM = wid >> 1, warpN = wid & 1, gid = lane >> 2, tq = lane & 3;
    int r0 = blockIdx.x * 128;
    int rb = warpM * 16;

    copy_w_async(Wp, sbase + SZ_AP * 4);
    CP_COMMIT();
    load_a_f32((const float4*)A, r0, n, AP);
    if (tid < 128) sb[tid] = bias[tid];
    CP_WAIT0();
    __syncthreads();

    float acc[8][4];
#pragma unroll
    for (int nt = 0; nt < 8; nt++)
#pragma unroll
        for (int j = 0; j < 4; j++) acc[nt][j] = 0.f;

    mma_tile(AP, WP, acc, rb, warpN, gid, tq);

#pragma unroll
    for (int p = 0; p < 2; p++) {
        int row = r0 + rb + p * 8 + gid;
        if (row >= n) continue;
#pragma unroll
        for (int nt = 0; nt < 8; nt++) {
            int cb = warpN * 64 + nt * 8 + 2 * tq;
            float2 o;
            o.x = acc[nt][2 * p + 0] + sb[cb];
            o.y = acc[nt][2 * p + 1] + sb[cb + 1];
            *(float2*)(C + (size_t)row * H + cb) = o;
            Ch[(size_t)row * 64 + (cb >> 1)] = f2h2(o.x, o.y);
        }
    }
}

// ---------------- multi-tile fused layer kernel (all 4 W panels resident) ----------------
__global__ __launch_bounds__(512) void tc_layer(
    const uint32_t* __restrict__ curh, const uint32_t* __restrict__ ngh,
    const uint4* __restrict__ Wsp, const uint4* __restrict__ Wnp,
    const uint4* __restrict__ WgAp, const uint4* __restrict__ WgBp,
    const float* __restrict__ bs, const float* __restrict__ bn, const float* __restrict__ bg,
    const float* __restrict__ coef,
    const float* __restrict__ gamma, const float* __restrict__ beta,
    float* __restrict__ Houtf, uint32_t* __restrict__ Houth, int n, int nTiles, int writef)
{
    extern __shared__ uint32_t smem[];
    uint32_t* Acur = smem;
    uint32_t* Am   = smem + L_OFF_AM;          // neigh tile, later m tile
    uint32_t* W0   = smem + L_OFF_W0;          // Ws | Wn | WgA | WgB resident
    float* sc  = (float*)(smem + L_OFF_SC);    // bs|bn|bg|gamma|beta
    float* lnb = sc + 640;
    uint32_t sbase = smem_u32(smem);

    int tid = threadIdx.x, wid = tid >> 5, lane = tid & 31;
    int warpM = wid >> 1, warpN = wid & 1, gid = lane >> 2, tq = lane & 3;
    int rb = warpM * 16;

    int t0 = blockIdx.x;
    if (t0 < nTiles) {
        copy_a_async(curh, t0 * 128, n, sbase);
        copy_a_async(ngh, t0 * 128, n, sbase + L_OFF_AM * 4);
    }
    copy_w_async(Wsp,  sbase + L_OFF_W0 * 4);
    copy_w_async(Wnp,  sbase + (L_OFF_W0 + SZ_WP) * 4);
    copy_w_async(WgAp, sbase + (L_OFF_W0 + 2 * SZ_WP) * 4);
    copy_w_async(WgBp, sbase + (L_OFF_W0 + 3 * SZ_WP) * 4);
    CP_COMMIT();
    if (tid < 128) {
        sc[tid] = bs[tid]; sc[128 + tid] = bn[tid]; sc[256 + tid] = bg[tid];
        sc[384 + tid] = gamma[tid]; sc[512 + tid] = beta[tid];
    }
    CP_WAIT0();
    __syncthreads();

    for (int tile = t0; tile < nTiles; tile += gridDim.x) {
        int r0 = tile * 128;

        float acc1[8][4], acc2[8][4];
#pragma unroll
        for (int nt = 0; nt < 8; nt++)
#pragma unroll
            for (int j = 0; j < 4; j++) { acc1[nt][j] = 0.f; acc2[nt][j] = 0.f; }

        // merged passes 1&3: one A-fragment stream feeds Ws->acc1 and WgA->acc2
        mma_tile2(Acur, W0, W0 + 2 * SZ_WP, acc1, acc2, rb, warpN, gid, tq);
        // pass 2: neigh @ Wn -> acc1
        mma_tile(Am, W0 + SZ_WP, acc1, rb, warpN, gid, tq);
        __syncthreads();   // all warps finished reading Am(neigh)

        // m = acc1 + bs + cf*bn (exact fp32 in regs); write half m over Am
#pragma unroll
        for (int p = 0; p < 2; p++) {
            int lrow = rb + p * 8 + gid;
            int row = r0 + lrow;
            if (row >= n) continue;
            float cf = coef[row];
#pragma unroll
            for (int nt = 0; nt < 8; nt++) {
                int cb = warpN * 64 + nt * 8 + 2 * tq;
                float v0 = acc1[nt][2 * p + 0] + sc[cb + 0] + cf * sc[128 + cb + 0];
                float v1 = acc1[nt][2 * p + 1] + sc[cb + 1] + cf * sc[128 + cb + 1];
                acc1[nt][2 * p + 0] = v0;
                acc1[nt][2 * p + 1] = v1;
                Am[lrow * AP_STRIDE + (cb >> 1)] = f2h2(v0, v1);
            }
        }
        __syncthreads();   // m visible
        mma_tile(Am, W0 + 3 * SZ_WP, acc2, rb, warpN, gid, tq);   // += m@WgB
        __syncthreads();   // all reads of Am complete (Acur still needed below)

        // epilogue: gate + blend (h from half mirror in Acur) + LN + ReLU
        float rsum[2] = {0.f, 0.f};
        float rsq[2] = {0.f, 0.f};
#pragma unroll
        for (int p = 0; p < 2; p++) {
            int lrow = rb + p * 8 + gid;
            int row = r0 + lrow;
            if (row >= n) continue;
#pragma unroll
            for (int nt = 0; nt < 8; nt++) {
                int cb = warpN * 64 + nt * 8 + 2 * tq;
                float2 hv = h2f2(Acur[lrow * AP_STRIDE + (cb >> 1)]);
                float pre, g, v;
                pre = acc2[nt][2 * p + 0] + sc[256 + cb];
                g = 1.f / (1.f + expf(-pre));
                v = g * acc1[nt][2 * p + 0] + (1.f - g) * hv.x;
                acc1[nt][2 * p + 0] = v; rsum[p] += v; rsq[p] += v * v;
                pre = acc2[nt][2 * p + 1] + sc[256 + cb + 1];
                g = 1.f / (1.f + expf(-pre));
                v = g * acc1[nt][2 * p + 1] + (1.f - g) * hv.y;
                acc1[nt][2 * p + 1] = v; rsum[p] += v; rsq[p] += v * v;
            }
        }
#pragma unroll
        for (int p = 0; p < 2; p++) {
            rsum[p] += __shfl_xor_sync(0xffffffffu, rsum[p], 1);
            rsum[p] += __shfl_xor_sync(0xffffffffu, rsum[p], 2);
            rsq[p] += __shfl_xor_sync(0xffffffffu, rsq[p], 1);
            rsq[p] += __shfl_xor_sync(0xffffffffu, rsq[p], 2);
        }
        if (tq == 0) {
#pragma unroll
            for (int p = 0; p < 2; p++) {
                int lrow = rb + p * 8 + gid;
                lnb[lrow * 4 + warpN * 2 + 0] = rsum[p];
                lnb[lrow * 4 + warpN * 2 + 1] = rsq[p];
            }
        }
        __syncthreads();   // lnb ready; ALL Acur reads complete

        // prefetch next tile's A pair (overlaps LN-store loop only; Acur no longer read)
        int tnext = tile + gridDim.x;
        if (tnext < nTiles) {
            copy_a_async(curh, tnext * 128, n, sbase);
            copy_a_async(ngh, tnext * 128, n, sbase + L_OFF_AM * 4);
            CP_COMMIT();
        }

#pragma unroll
        for (int p = 0; p < 2; p++) {
            int lrow = rb + p * 8 + gid;
            int row = r0 + lrow;
            if (row >= n) continue;
            float sum = lnb[lrow * 4 + 0] + lnb[lrow * 4 + 2];
            float sq  = lnb[lrow * 4 + 1] + lnb[lrow * 4 + 3];
            float mu = sum * (1.f / 128.f);
            float var = sq * (1.f / 128.f) - mu * mu;
            float rs = rsqrtf(var + 1e-5f);
            float* orow = Houtf + (size_t)row * H;
#pragma unroll
            for (int nt = 0; nt < 8; nt++) {
                int cb = warpN * 64 + nt * 8 + 2 * tq;
                float2 o;
                o.x = fmaxf(fmaf((acc1[nt][2 * p + 0] - mu) * rs, sc[384 + cb], sc[512 + cb]), 0.f);
                o.y = fmaxf(fmaf((acc1[nt][2 * p + 1] - mu) * rs, sc[384 + cb + 1], sc[512 + cb + 1]), 0.f);
                if (writef) *(float2*)(orow + cb) = o;
                Houth[(size_t)row * 64 + (cb >> 1)] = f2h2(o.x, o.y);
            }
        }
        if (tnext < nTiles) CP_WAIT0();
        __syncthreads();
    }
}

// ---------------- fused attention score ----------------
__global__ __launch_bounds__(512) void tc_score(
    const uint32_t* __restrict__ Ah, const uint4* __restrict__ Wp,
    const float* __restrict__ bias, const float* __restrict__ Wsc,
    const float* __restrict__ bsc, int n)
{
    extern __shared__ uint32_t smem[];
    uint32_t* AP = smem;
    uint32_t* WP = smem + SZ_AP;
    float* sb = (float*)(smem + SZ_AP + SZ_WP);
    float* sw = sb + 128;
    float* lnb = sw + 128;
    uint32_t sbase = smem_u32(smem);

    int tid = threadIdx.x, wid = tid >> 5, lane = tid & 31;
    int warpM = wid >> 1, warpN = wid & 1, gid = lane >> 2, tq = lane & 3;
    int r0 = blockIdx.x * 128;
    int rb = warpM * 16;

    copy_a_async(Ah, r0, n, sbase);
    copy_w_async(Wp, sbase + SZ_AP * 4);
    if (tid < 128) sb[tid] = bias[tid];
    else if (tid < 256) sw[tid - 128] = Wsc[tid - 128];
    CP_COMMIT(); CP_WAIT0();
    __syncthreads();

    float acc[8][4];
#pragma unroll
    for (int nt = 0; nt < 8; nt++)
#pragma unroll
        for (int j = 0; j < 4; j++) acc[nt][j] = 0.f;

    mma_tile(AP, WP, acc, rb, warpN, gid, tq);

    float part[2] = {0.f, 0.f};
#pragma unroll
    for (int nt = 0; nt < 8; nt++) {
        int cb = warpN * 64 + nt * 8 + 2 * tq;
#pragma unroll
        for (int p = 0; p < 2; p++) {
            part[p] += tanhf(acc[nt][2 * p + 0] + sb[cb]) * sw[cb];
            part[p] += tanhf(acc[nt][2 * p + 1] + sb[cb + 1]) * sw[cb + 1];
        }
    }
#pragma unroll
    for (int p = 0; p < 2; p++) {
        part[p] += __shfl_xor_sync(0xffffffffu, part[p], 1);
        part[p] += __shfl_xor_sync(0xffffffffu, part[p], 2);
    }
    if (tq == 0) {
#pragma unroll
        for (int p = 0; p < 2; p++) {
            int lrow = rb + p * 8 + gid;
            lnb[lrow * 2 + warpN] = part[p];
        }
    }
    __syncthreads();
    if (warpN == 0 && tq == 0) {
#pragma unroll
        for (int p = 0; p < 2; p++) {
            int lrow = rb + p * 8 + gid;
            int row = r0 + lrow;
            if (row >= n) continue;
            float scv = lnb[lrow * 2 + 0] + lnb[lrow * 2 + 1] + bsc[0];
            bool sink = (g_outdeg[row] == 0);
            g_scores[row] = sink ? scv : neg_inf();
            if (sink) atomicMax(&g_maxbits, encf(scv));
        }
    }
}

// ---------------- graph prep ----------------
__global__ void zero_kernel(int n) {
    int i = blockIdx.x * blockDim.x + threadIdx.x;
    if (i < n) { g_indeg[i] = 0; g_outdeg[i] = 0; g_cursor[i] = 0; }
    if (i < H) g_emb[i] = 0.f;
    if (i == 0) { g_maxbits = encf(neg_inf()); g_sumexp = 0.f; }
}
__global__ void deg_kernel(const int* __restrict__ src, const int* __restrict__ dst, int e) {
    int i = blockIdx.x * blockDim.x + threadIdx.x;
    if (i < e) { atomicAdd(&g_indeg[dst[i]], 1); atomicAdd(&g_outdeg[src[i]], 1); }
}
__global__ void prep_kernel(int n) {
    int i = blockIdx.x * blockDim.x + threadIdx.x;
    if (i < n) {
        int d = g_indeg[i];
        g_hp[i] = d > 0 ? 1.f : 0.f;
        g_invdeg[i] = 1.f / (float)(d > 0 ? d : 1);
    }
}
__global__ void scan1_kernel(int n) {
    __shared__ int sm[1024];
    int t = threadIdx.x;
    int i = blockIdx.x * 1024 + t;
    int v = (i < n) ? g_indeg[i] : 0;
    sm[t] = v;
    __syncthreads();
    for (int off = 1; off < 1024; off <<= 1) {
        int x = (t >= off) ? sm[t - off] : 0;
        __syncthreads();
        sm[t] += x;
        __syncthreads();
    }
    if (i < n) g_off[i] = sm[t] - v;
    if (t == 1023) g_bsum[blockIdx.x] = sm[1023];
}
__global__ void scan2_kernel(int nb) {
    if (threadIdx.x == 0) {
        int c = 0;
        for (int i = 0; i < nb; i++) { int x = g_bsum[i]; g_bsum[i] = c; c += x; }
    }
}
__global__ void scan3_kernel(int n) {
    int i = blockIdx.x * blockDim.x + threadIdx.x;
    if (i < n) g_off[i] += g_bsum[i >> 10];
}
__global__ void fill_kernel(const int* __restrict__ src, const int* __restrict__ dst, int e) {
    int i = blockIdx.x * blockDim.x + threadIdx.x;
    if (i < e) {
        int d = dst[i];
        int p = g_off[d] + atomicAdd(&g_cursor[d], 1);
        g_csr[p] = src[i];
    }
}

// ---------------- neighbor mean (half in, half out, fp32 accumulate) ----------------
__global__ void neigh_kernel(const uint32_t* __restrict__ Hh, uint32_t* __restrict__ Ngh, int n) {
    int gw = (blockIdx.x * blockDim.x + threadIdx.x) >> 5;
    int lane = threadIdx.x & 31;
    if (gw >= n) return;
    int start = g_off[gw];
    int deg = g_indeg[gw];
    const uint2* H2 = (const uint2*)Hh;
    float4 acc = make_float4(0.f, 0.f, 0.f, 0.f);
    for (int base = 0; base < deg; base += 32) {
        int e = base + lane;
        int s = (e < deg) ? g_csr[start + e] : 0;
        int cnt = min(32, deg - base);
        for (int j = 0; j < cnt; j++) {
            int sj = __shfl_sync(0xffffffffu, s, j);
            uint2 v = H2[(size_t)sj * 32 + lane];
            float2 f0 = h2f2(v.x), f1 = h2f2(v.y);
            acc.x += f0.x; acc.y += f0.y; acc.z += f1.x; acc.w += f1.y;
        }
    }
    float iv = g_invdeg[gw];
    uint2 o;
    o.x = f2h2(acc.x * iv, acc.y * iv);
    o.y = f2h2(acc.z * iv, acc.w * iv);
    ((uint2*)Ngh)[(size_t)gw * 32 + lane] = o;
}

// ---------------- pooling ----------------
__global__ void pool2_kernel(const float* __restrict__ Hin, int n) {
    __shared__ float sb[8 * 128];
    __shared__ float se[8];
    int tid = threadIdx.x, w = tid >> 5, lane = tid & 31;
    int gw = (blockIdx.x * blockDim.x + tid) >> 5;
    int nw = (gridDim.x * blockDim.x) >> 5;
    float mx = decf(g_maxbits);
    const float4* H4 = (const float4*)Hin;
    float4 acc = make_float4(0.f, 0.f, 0.f, 0.f);
    float es = 0.f;
    for (int i = gw; i < n; i += nw) {
        float s = g_scores[i];
        if (s >= -1e30f) {
            float e = expf(s - mx);
            if (lane == 0) es += e;
            float4 hv = H4[(size_t)i * 32 + lane];
            acc.x += e * hv.x; acc.y += e * hv.y; acc.z += e * hv.z; acc.w += e * hv.w;
        }
    }
    *(float4*)&sb[w * 128 + lane * 4] = acc;
    if (lane == 0) se[w] = es;
    __syncthreads();
    if (tid < 128) {
        float t = 0.f;
#pragma unroll
        for (int j = 0; j < 8; j++) t += sb[j * 128 + tid];
        if (t != 0.f) atomicAdd(&g_emb[tid], t);
    }
    if (tid == 0) {
        float t = 0.f;
#pragma unroll
        for (int j = 0; j < 8; j++) t += se[j];
        if (t != 0.f) atomicAdd(&g_sumexp, t);
    }
}
__global__ void finish_kernel(float* __restrict__ gout) {
    int t = threadIdx.x;
    gout[t] = g_emb[t] / g_sumexp;
}

// ---------------- launch ----------------
extern "C" void kernel_launch(void* const* d_in, const int* in_sizes, int n_in,
                              void* d_out, int out_size)
{
    const float* node_feats = (const float*)d_in[0];
    const int*   src        = (const int*)d_in[1];
    const int*   dst        = (const int*)d_in[2];
    const float* W_in       = (const float*)d_in[3];
    const float* b_in       = (const float*)d_in[4];
    const float* Ws         = (const float*)d_in[5];
    const float* bs         = (const float*)d_in[6];
    const float* Wn         = (const float*)d_in[7];
    const float* bn         = (const float*)d_in[8];
    const float* Wg         = (const float*)d_in[9];
    const float* bg         = (const float*)d_in[10];
    const float* gamma      = (const float*)d_in[11];
    const float* beta       = (const float*)d_in[12];
    const float* W_att      = (const float*)d_in[13];
    const float* b_att      = (const float*)d_in[14];
    const float* W_score    = (const float*)d_in[15];
    const float* b_score    = (const float*)d_in[16];

    int n = in_sizes[0] / H;
    int e = in_sizes[1];
    int L = in_sizes[6] / H;

    float* out_h = (float*)d_out;
    float* out_g = out_h + (size_t)n * H;

    float *hA, *hp;
    uint32_t *hAh, *hBh, *ngh;
    uint4* Wh;
    cudaGetSymbolAddress((void**)&hA, g_hA);
    cudaGetSymbolAddress((void**)&hAh, g_hAh);
    cudaGetSymbolAddress((void**)&hBh, g_hBh);
    cudaGetSymbolAddress((void**)&ngh, g_ngh);
    cudaGetSymbolAddress((void**)&hp, g_hp);
    cudaGetSymbolAddress((void**)&Wh, g_Wh4);

    cudaFuncSetAttribute(tc_gemm,  cudaFuncAttributeMaxDynamicSharedMemorySize, GSMEM_BYTES);
    cudaFuncSetAttribute(tc_score, cudaFuncAttributeMaxDynamicSharedMemorySize, SSMEM_BYTES);
    cudaFuncSetAttribute(tc_layer, cudaFuncAttributeMaxDynamicSharedMemorySize, LSMEM_BYTES);

    int nbN = (n + 255) / 256;
    int nbE = (e + 255) / 256;
    int nbT = (n + 127) / 128;
    int nbW = (n + 7) / 8;
    int nbS = (n + 1023) / 1024;
    int wtotal = (4 * L + 2) * 8192;

    // launch order keeps tc_gemm 4th (ncu capture slot)
    wconv_kernel<<<(wtotal + 255) / 256, 256>>>(W_in, Ws, Wn, Wg, W_att, L);
    zero_kernel<<<nbN, 256>>>(n);
    deg_kernel<<<nbE, 256>>>(src, dst, e);
    tc_gemm<<<nbT, 512, GSMEM_BYTES>>>(node_feats, Wh, b_in, hA, hAh, n);
    prep_kernel<<<nbN, 256>>>(n);
    scan1_kernel<<<nbS, 1024>>>(n);
    scan2_kernel<<<1, 32>>>(nbS);
    scan3_kernel<<<nbN, 256>>>(n);
    fill_kernel<<<nbE, 256>>>(src, dst, e);

    uint32_t* curh = hAh;
    uint32_t* otherh = hBh;
    for (int i = 0; i < L; i++) {
        const uint4* Wsp  = Wh + (size_t)(1 + i) * 2048;
        const uint4* Wnp  = Wh + (size_t)(1 + L + i) * 2048;
        const uint4* WgAp = Wh + (size_t)(1 + 2 * L + i) * 2048;
        const uint4* WgBp = Wh + (size_t)(1 + 3 * L + i) * 2048;
        const float* bs_i = bs + (size_t)i * H;
        const float* bn_i = bn + (size_t)i * H;
        const float* bg_i = bg + (size_t)i * H;
        const float* ga_i = gamma + (size_t)i * H;
        const float* be_i = beta + (size_t)i * H;

        neigh_kernel<<<nbW, 256>>>(curh, ngh, n);
        int last = (i == L - 1);
        tc_layer<<<148, 512, LSMEM_BYTES>>>(curh, ngh, Wsp, Wnp, WgAp, WgBp,
                                            bs_i, bn_i, bg_i, hp, ga_i, be_i,
                                            out_h, otherh, n, nbT, last);
        uint32_t* th = curh; curh = otherh; otherh = th;
    }

    tc_score<<<nbT, 512, SSMEM_BYTES>>>(curh, Wh + (size_t)(4 * L + 1) * 2048,
                                        b_att, W_score, b_score, n);
    pool2_kernel<<<64, 256>>>(out_h, n);
    finish_kernel<<<1, 128>>>(out_g);
}

// round 14
// speedup vs baseline: 1.3195x; 1.0033x over previous
#include <cuda_runtime.h>
#include <cuda_fp16.h>
#include <math.h>
#include <stdint.h>

#define MAXN 100000
#define MAXE 800000
#define H 128
#define NPAD (MAXN + 128)

// ---------------- device scratch ----------------
__device__ float g_hA[(size_t)MAXN * H];
__device__ uint32_t g_hAh[(size_t)NPAD * 64];   // half2 k-pair mirrors
__device__ uint32_t g_hBh[(size_t)NPAD * 64];
__device__ uint32_t g_ngh[(size_t)NPAD * 64];
__device__ uint4 g_Wh4[16 * 2048];              // preconverted weight panels (half2 kpair)
__device__ int   g_indeg[MAXN];
__device__ int   g_outdeg[MAXN];
__device__ int   g_cursor[MAXN];
__device__ int   g_off[MAXN];
__device__ int   g_csr[MAXE];
__device__ int   g_bsum[128];
__device__ float g_hp[MAXN];
__device__ float g_invdeg[MAXN];
__device__ float g_scores[MAXN];
__device__ float g_emb[H];
__device__ float g_sumexp;
__device__ unsigned g_maxbits;

__device__ __forceinline__ float neg_inf() { return __int_as_float(0xff800000); }
__device__ __forceinline__ unsigned encf(float f) {
    unsigned u = __float_as_uint(f);
    return (u & 0x80000000u) ? ~u : (u | 0x80000000u);
}
__device__ __forceinline__ float decf(unsigned u) {
    return (u & 0x80000000u) ? __uint_as_float(u ^ 0x80000000u) : __uint_as_float(~u);
}

// ---------------- fp16 helpers ----------------
__device__ __forceinline__ uint32_t f2h2(float a, float b) {
    __half2 h = __floats2half2_rn(a, b);
    return *(uint32_t*)&h;
}
__device__ __forceinline__ float2 h2f2(uint32_t u) {
    __half2 h = *(__half2*)&u;
    return __half22float2(h);
}
__device__ __forceinline__ void mma16816(float* c, uint32_t a0, uint32_t a1, uint32_t a2, uint32_t a3,
                                         uint32_t b0, uint32_t b1) {
    asm volatile("mma.sync.aligned.m16n8k16.row.col.f32.f16.f16.f32 "
                 "{%0,%1,%2,%3}, {%4,%5,%6,%7}, {%8,%9}, {%0,%1,%2,%3};"
                 : "+f"(c[0]), "+f"(c[1]), "+f"(c[2]), "+f"(c[3])
                 : "r"(a0), "r"(a1), "r"(a2), "r"(a3), "r"(b0), "r"(b1));
}
__device__ __forceinline__ uint32_t smem_u32(const void* p) {
    uint32_t a;
    asm("{ .reg .u64 t; cvta.to.shared.u64 t, %1; cvt.u32.u64 %0, t; }" : "=r"(a) : "l"(p));
    return a;
}
#define CP_COMMIT() asm volatile("cp.async.commit_group;" ::: "memory")
#define CP_WAIT0()  asm volatile("cp.async.wait_group 0;" ::: "memory")
#define PAIR_BAR(warpM) asm volatile("bar.sync %0, 64;" :: "r"(1 + (warpM)) : "memory")

// A tile: 128 rows x 64 half2, stride 68 u32.  W tile: 64 kp-rows x 128 half2, stride 136 u32.
#define AP_STRIDE 68
#define WP_STRIDE 136
#define SZ_AP (128 * AP_STRIDE)     // 8704 u32
#define SZ_WP (64 * WP_STRIDE)      // 8704 u32
#define GSMEM_BYTES ((SZ_AP + SZ_WP + 128) * 4)
#define SSMEM_BYTES ((SZ_AP + SZ_WP + 512) * 4)
// tc_layer (multi-tile): Acur | Am | W0..W3 | consts | lnbuf
#define L_OFF_AM   SZ_AP
#define L_OFF_W0   (2 * SZ_AP)
#define L_OFF_SC   (2 * SZ_AP + 4 * SZ_WP)
#define LSMEM_BYTES ((2 * SZ_AP + 4 * SZ_WP + 640 + 512) * 4)

// ---------------- tile loaders (512-thread CTAs) ----------------
__device__ __forceinline__ void load_a_f32(const float4* __restrict__ G, int r0, int n, uint32_t* sm) {
    int t = threadIdx.x;
#pragma unroll
    for (int i = 0; i < 8; i++) {
        int g = t + i * 512;
        int row = g >> 5, c4 = g & 31;
        float4 v = make_float4(0.f, 0.f, 0.f, 0.f);
        if (r0 + row < n) v = G[(size_t)(r0 + row) * 32 + c4];
        uint2 w;
        w.x = f2h2(v.x, v.y);
        w.y = f2h2(v.z, v.w);
        *(uint2*)(sm + row * AP_STRIDE + c4 * 2) = w;
    }
}
__device__ __forceinline__ void copy_a_async(const uint32_t* __restrict__ src, int r0, int n, uint32_t dstb) {
    int t = threadIdx.x;
#pragma unroll
    for (int i = 0; i < 4; i++) {
        int g = t + i * 512;
        int row = g >> 4, q = g & 15;
        uint32_t dst = dstb + (uint32_t)(row * AP_STRIDE + q * 4) * 4u;
        const uint32_t* s = src + (size_t)(r0 + row) * 64 + q * 4;
        int sz = (r0 + row < n) ? 16 : 0;
        asm volatile("cp.async.cg.shared.global [%0], [%1], 16, %2;" :: "r"(dst), "l"(s), "r"(sz));
    }
}
__device__ __forceinline__ void copy_w_async(const uint4* __restrict__ src, uint32_t dstb) {
    int t = threadIdx.x;
#pragma unroll
    for (int i = 0; i < 4; i++) {
        int g = t + i * 512;
        int kp = g >> 5, c4 = g & 31;
        uint32_t dst = dstb + (uint32_t)(kp * WP_STRIDE + c4 * 4) * 4u;
        asm volatile("cp.async.cg.shared.global [%0], [%1], 16;" :: "r"(dst), "l"(src + kp * 32 + c4));
    }
}

// warp-tile MMA: 16 warps, each 16 rows x 64 cols -> acc[8][4]
__device__ __forceinline__ void mma_tile(const uint32_t* AP, const uint32_t* WP,
                                         float acc[8][4], int rb, int warpN,
                                         int gid, int tq) {
#pragma unroll
    for (int ks = 0; ks < 8; ks++) {
        int kp0 = ks * 8;
        uint32_t a0 = AP[(rb + gid) * AP_STRIDE + kp0 + tq];
        uint32_t a1 = AP[(rb + gid + 8) * AP_STRIDE + kp0 + tq];
        uint32_t a2 = AP[(rb + gid) * AP_STRIDE + kp0 + tq + 4];
        uint32_t a3 = AP[(rb + gid + 8) * AP_STRIDE + kp0 + tq + 4];
#pragma unroll
        for (int nt = 0; nt < 8; nt++) {
            int cb = warpN * 64 + nt * 8 + gid;
            uint32_t b0 = WP[(kp0 + tq) * WP_STRIDE + cb];
            uint32_t b1 = WP[(kp0 + tq + 4) * WP_STRIDE + cb];
            mma16816(acc[nt], a0, a1, a2, a3, b0, b1);
        }
    }
}

// dual-pass MMA: shared A fragments feed two weight panels (acc1 += A@W1, acc2 += A@W2)
__device__ __forceinline__ void mma_tile2(const uint32_t* AP, const uint32_t* W1, const uint32_t* W2,
                                          float acc1[8][4], float acc2[8][4], int rb, int warpN,
                                          int gid, int tq) {
#pragma unroll
    for (int ks = 0; ks < 8; ks++) {
        int kp0 = ks * 8;
        uint32_t a0 = AP[(rb + gid) * AP_STRIDE + kp0 + tq];
        uint32_t a1 = AP[(rb + gid + 8) * AP_STRIDE + kp0 + tq];
        uint32_t a2 = AP[(rb + gid) * AP_STRIDE + kp0 + tq + 4];
        uint32_t a3 = AP[(rb + gid + 8) * AP_STRIDE + kp0 + tq + 4];
#pragma unroll
        for (int nt = 0; nt < 8; nt++) {
            int cb = warpN * 64 + nt * 8 + gid;
            uint32_t b0 = W1[(kp0 + tq) * WP_STRIDE + cb];
            uint32_t b1 = W1[(kp0 + tq + 4) * WP_STRIDE + cb];
            mma16816(acc1[nt], a0, a1, a2, a3, b0, b1);
            uint32_t c0 = W2[(kp0 + tq) * WP_STRIDE + cb];
            uint32_t c1 = W2[(kp0 + tq + 4) * WP_STRIDE + cb];
            mma16816(acc2[nt], a0, a1, a2, a3, c0, c1);
        }
    }
}

// ---------------- weight preconversion ----------------
__global__ void wconv_kernel(const float* __restrict__ W_in, const float* __restrict__ Ws,
                             const float* __restrict__ Wn, const float* __restrict__ Wg,
                             const float* __restrict__ W_att, int L) {
    int idx = blockIdx.x * blockDim.x + threadIdx.x;
    int total = (4 * L + 2) * 8192;
    if (idx >= total) return;
    int p = idx >> 13;
    int j = idx & 8191;
    int kp = j >> 7, nn = j & 127;
    const float* src;
    if (p == 0) src = W_in;
    else if (p <= L) src = Ws + (size_t)(p - 1) * H * H;
    else if (p <= 2 * L) src = Wn + (size_t)(p - 1 - L) * H * H;
    else if (p <= 3 * L) src = Wg + (size_t)(p - 1 - 2 * L) * 2 * H * H;
    else if (p <= 4 * L) src = Wg + (size_t)(p - 1 - 3 * L) * 2 * H * H + (size_t)H * H;
    else src = W_att;
    ((uint32_t*)g_Wh4)[idx] = f2h2(src[(size_t)(2 * kp) * H + nn], src[(size_t)(2 * kp + 1) * H + nn]);
}

// ---------------- GEMM (input projection): C = A@W + bias, + half mirror ----------------
__global__ __launch_bounds__(512) void tc_gemm(
    const float* __restrict__ A, const uint4* __restrict__ Wp,
    const float* __restrict__ bias, float* __restrict__ C, uint32_t* __restrict__ Ch, int n)
{
    extern __shared__ uint32_t smem[];
    uint32_t* AP = smem;
    uint32_t* WP = smem + SZ_AP;
    float* sb = (float*)(smem + SZ_AP + SZ_WP);
    uint32_t sbase = smem_u32(smem);

    int tid = threadIdx.x, wid = tid >> 5, lane = tid & 31;
    int warpM = wid >> 1, warpN = wid & 1, gid = lane >> 2, tq = lane & 3;
    int r0 = blockIdx.x * 128;
    int rb = warpM * 16;

    copy_w_async(Wp, sbase + SZ_AP * 4);
    CP_COMMIT();
    load_a_f32((const float4*)A, r0, n, AP);
    if (tid < 128) sb[tid] = bias[tid];
    CP_WAIT0();
    __syncthreads();

    float acc[8][4];
#pragma unroll
    for (int nt = 0; nt < 8; nt++)
#pragma unroll
        for (int j = 0; j < 4; j++) acc[nt][j] = 0.f;

    mma_tile(AP, WP, acc, rb, warpN, gid, tq);

#pragma unroll
    for (int p = 0; p < 2; p++) {
        int row = r0 + rb + p * 8 + gid;
        if (row >= n) continue;
#pragma unroll
        for (int nt = 0; nt < 8; nt++) {
            int cb = warpN * 64 + nt * 8 + 2 * tq;
            float2 o;
            o.x = acc[nt][2 * p + 0] + sb[cb];
            o.y = acc[nt][2 * p + 1] + sb[cb + 1];
            *(float2*)(C + (size_t)row * H + cb) = o;
            Ch[(size_t)row * 64 + (cb >> 1)] = f2h2(o.x, o.y);
        }
    }
}

// ---------------- multi-tile fused layer kernel (all 4 W panels resident) ----------------
__global__ __launch_bounds__(512) void tc_layer(
    const uint32_t* __restrict__ curh, const uint32_t* __restrict__ ngh,
    const uint4* __restrict__ Wsp, const uint4* __restrict__ Wnp,
    const uint4* __restrict__ WgAp, const uint4* __restrict__ WgBp,
    const float* __restrict__ bs, const float* __restrict__ bn, const float* __restrict__ bg,
    const float* __restrict__ coef,
    const float* __restrict__ gamma, const float* __restrict__ beta,
    float* __restrict__ Houtf, uint32_t* __restrict__ Houth, int n, int nTiles, int writef)
{
    extern __shared__ uint32_t smem[];
    uint32_t* Acur = smem;
    uint32_t* Am   = smem + L_OFF_AM;          // neigh tile, later m tile
    uint32_t* W0   = smem + L_OFF_W0;          // Ws | Wn | WgA | WgB resident
    float* sc  = (float*)(smem + L_OFF_SC);    // bs|bn|bg|gamma|beta
    float* lnb = sc + 640;
    uint32_t sbase = smem_u32(smem);

    int tid = threadIdx.x, wid = tid >> 5, lane = tid & 31;
    int warpM = wid >> 1, warpN = wid & 1, gid = lane >> 2, tq = lane & 3;
    int rb = warpM * 16;

    int t0 = blockIdx.x;
    if (t0 < nTiles) {
        copy_a_async(curh, t0 * 128, n, sbase);
        copy_a_async(ngh, t0 * 128, n, sbase + L_OFF_AM * 4);
    }
    copy_w_async(Wsp,  sbase + L_OFF_W0 * 4);
    copy_w_async(Wnp,  sbase + (L_OFF_W0 + SZ_WP) * 4);
    copy_w_async(WgAp, sbase + (L_OFF_W0 + 2 * SZ_WP) * 4);
    copy_w_async(WgBp, sbase + (L_OFF_W0 + 3 * SZ_WP) * 4);
    CP_COMMIT();
    if (tid < 128) {
        sc[tid] = bs[tid]; sc[128 + tid] = bn[tid]; sc[256 + tid] = bg[tid];
        sc[384 + tid] = gamma[tid]; sc[512 + tid] = beta[tid];
    }
    CP_WAIT0();
    __syncthreads();

    for (int tile = t0; tile < nTiles; tile += gridDim.x) {
        int r0 = tile * 128;

        float acc1[8][4], acc2[8][4];
#pragma unroll
        for (int nt = 0; nt < 8; nt++)
#pragma unroll
            for (int j = 0; j < 4; j++) { acc1[nt][j] = 0.f; acc2[nt][j] = 0.f; }

        // merged passes 1&3: one A-fragment stream feeds Ws->acc1 and WgA->acc2
        mma_tile2(Acur, W0, W0 + 2 * SZ_WP, acc1, acc2, rb, warpN, gid, tq);
        // pass 2: neigh @ Wn -> acc1  (reads only this warp's 16 rows of Am)
        mma_tile(Am, W0 + SZ_WP, acc1, rb, warpN, gid, tq);
        PAIR_BAR(warpM);   // pair-scope: partner finished reading Am rows rb..rb+15

        // m = acc1 + bs + cf*bn (exact fp32 in regs); write half m over Am
#pragma unroll
        for (int p = 0; p < 2; p++) {
            int lrow = rb + p * 8 + gid;
            int row = r0 + lrow;
            if (row >= n) continue;
            float cf = coef[row];
#pragma unroll
            for (int nt = 0; nt < 8; nt++) {
                int cb = warpN * 64 + nt * 8 + 2 * tq;
                float v0 = acc1[nt][2 * p + 0] + sc[cb + 0] + cf * sc[128 + cb + 0];
                float v1 = acc1[nt][2 * p + 1] + sc[cb + 1] + cf * sc[128 + cb + 1];
                acc1[nt][2 * p + 0] = v0;
                acc1[nt][2 * p + 1] = v1;
                Am[lrow * AP_STRIDE + (cb >> 1)] = f2h2(v0, v1);
            }
        }
        PAIR_BAR(warpM);   // pair-scope: both column halves of m rows rb..rb+15 visible
        mma_tile(Am, W0 + 3 * SZ_WP, acc2, rb, warpN, gid, tq);   // += m@WgB

        // epilogue: gate + blend (h from half mirror in Acur) + LN + ReLU
        float rsum[2] = {0.f, 0.f};
        float rsq[2] = {0.f, 0.f};
#pragma unroll
        for (int p = 0; p < 2; p++) {
            int lrow = rb + p * 8 + gid;
            int row = r0 + lrow;
            if (row >= n) continue;
#pragma unroll
            for (int nt = 0; nt < 8; nt++) {
                int cb = warpN * 64 + nt * 8 + 2 * tq;
                float2 hv = h2f2(Acur[lrow * AP_STRIDE + (cb >> 1)]);
                float pre, g, v;
                pre = acc2[nt][2 * p + 0] + sc[256 + cb];
                g = 1.f / (1.f + expf(-pre));
                v = g * acc1[nt][2 * p + 0] + (1.f - g) * hv.x;
                acc1[nt][2 * p + 0] = v; rsum[p] += v; rsq[p] += v * v;
                pre = acc2[nt][2 * p + 1] + sc[256 + cb + 1];
                g = 1.f / (1.f + expf(-pre));
                v = g * acc1[nt][2 * p + 1] + (1.f - g) * hv.y;
                acc1[nt][2 * p + 1] = v; rsum[p] += v; rsq[p] += v * v;
            }
        }
#pragma unroll
        for (int p = 0; p < 2; p++) {
            rsum[p] += __shfl_xor_sync(0xffffffffu, rsum[p], 1);
            rsum[p] += __shfl_xor_sync(0xffffffffu, rsum[p], 2);
            rsq[p] += __shfl_xor_sync(0xffffffffu, rsq[p], 1);
            rsq[p] += __shfl_xor_sync(0xffffffffu, rsq[p], 2);
        }
        if (tq == 0) {
#pragma unroll
            for (int p = 0; p < 2; p++) {
                int lrow = rb + p * 8 + gid;
                lnb[lrow * 4 + warpN * 2 + 0] = rsum[p];
                lnb[lrow * 4 + warpN * 2 + 1] = rsq[p];
            }
        }
        __syncthreads();   // full: lnb visible; ALL Acur/Am reads complete

        // prefetch next tile's A pair (overlaps LN-store loop; Acur/Am no longer read)
        int tnext = tile + gridDim.x;
        if (tnext < nTiles) {
            copy_a_async(curh, tnext * 128, n, sbase);
            copy_a_async(ngh, tnext * 128, n, sbase + L_OFF_AM * 4);
            CP_COMMIT();
        }

#pragma unroll
        for (int p = 0; p < 2; p++) {
            int lrow = rb + p * 8 + gid;
            int row = r0 + lrow;
            if (row >= n) continue;
            float sum = lnb[lrow * 4 + 0] + lnb[lrow * 4 + 2];
            float sq  = lnb[lrow * 4 + 1] + lnb[lrow * 4 + 3];
            float mu = sum * (1.f / 128.f);
            float var = sq * (1.f / 128.f) - mu * mu;
            float rs = rsqrtf(var + 1e-5f);
            float* orow = Houtf + (size_t)row * H;
#pragma unroll
            for (int nt = 0; nt < 8; nt++) {
                int cb = warpN * 64 + nt * 8 + 2 * tq;
                float2 o;
                o.x = fmaxf(fmaf((acc1[nt][2 * p + 0] - mu) * rs, sc[384 + cb], sc[512 + cb]), 0.f);
                o.y = fmaxf(fmaf((acc1[nt][2 * p + 1] - mu) * rs, sc[384 + cb + 1], sc[512 + cb + 1]), 0.f);
                if (writef) *(float2*)(orow + cb) = o;
                Houth[(size_t)row * 64 + (cb >> 1)] = f2h2(o.x, o.y);
            }
        }
        if (tnext < nTiles) CP_WAIT0();
        __syncthreads();
    }
}

// ---------------- fused attention score ----------------
__global__ __launch_bounds__(512) void tc_score(
    const uint32_t* __restrict__ Ah, const uint4* __restrict__ Wp,
    const float* __restrict__ bias, const float* __restrict__ Wsc,
    const float* __restrict__ bsc, int n)
{
    extern __shared__ uint32_t smem[];
    uint32_t* AP = smem;
    uint32_t* WP = smem + SZ_AP;
    float* sb = (float*)(smem + SZ_AP + SZ_WP);
    float* sw = sb + 128;
    float* lnb = sw + 128;
    uint32_t sbase = smem_u32(smem);

    int tid = threadIdx.x, wid = tid >> 5, lane = tid & 31;
    int warpM = wid >> 1, warpN = wid & 1, gid = lane >> 2, tq = lane & 3;
    int r0 = blockIdx.x * 128;
    int rb = warpM * 16;

    copy_a_async(Ah, r0, n, sbase);
    copy_w_async(Wp, sbase + SZ_AP * 4);
    if (tid < 128) sb[tid] = bias[tid];
    else if (tid < 256) sw[tid - 128] = Wsc[tid - 128];
    CP_COMMIT(); CP_WAIT0();
    __syncthreads();

    float acc[8][4];
#pragma unroll
    for (int nt = 0; nt < 8; nt++)
#pragma unroll
        for (int j = 0; j < 4; j++) acc[nt][j] = 0.f;

    mma_tile(AP, WP, acc, rb, warpN, gid, tq);

    float part[2] = {0.f, 0.f};
#pragma unroll
    for (int nt = 0; nt < 8; nt++) {
        int cb = warpN * 64 + nt * 8 + 2 * tq;
#pragma unroll
        for (int p = 0; p < 2; p++) {
            part[p] += tanhf(acc[nt][2 * p + 0] + sb[cb]) * sw[cb];
            part[p] += tanhf(acc[nt][2 * p + 1] + sb[cb + 1]) * sw[cb + 1];
        }
    }
#pragma unroll
    for (int p = 0; p < 2; p++) {
        part[p] += __shfl_xor_sync(0xffffffffu, part[p], 1);
        part[p] += __shfl_xor_sync(0xffffffffu, part[p], 2);
    }
    if (tq == 0) {
#pragma unroll
        for (int p = 0; p < 2; p++) {
            int lrow = rb + p * 8 + gid;
            lnb[lrow * 2 + warpN] = part[p];
        }
    }
    __syncthreads();
    if (warpN == 0 && tq == 0) {
#pragma unroll
        for (int p = 0; p < 2; p++) {
            int lrow = rb + p * 8 + gid;
            int row = r0 + lrow;
            if (row >= n) continue;
            float scv = lnb[lrow * 2 + 0] + lnb[lrow * 2 + 1] + bsc[0];
            bool sink = (g_outdeg[row] == 0);
            g_scores[row] = sink ? scv : neg_inf();
            if (sink) atomicMax(&g_maxbits, encf(scv));
        }
    }
}

// ---------------- graph prep ----------------
__global__ void zero_kernel(int n) {
    int i = blockIdx.x * blockDim.x + threadIdx.x;
    if (i < n) { g_indeg[i] = 0; g_outdeg[i] = 0; g_cursor[i] = 0; }
    if (i < H) g_emb[i] = 0.f;
    if (i == 0) { g_maxbits = encf(neg_inf()); g_sumexp = 0.f; }
}
__global__ void deg_kernel(const int* __restrict__ src, const int* __restrict__ dst, int e) {
    int i = blockIdx.x * blockDim.x + threadIdx.x;
    if (i < e) { atomicAdd(&g_indeg[dst[i]], 1); atomicAdd(&g_outdeg[src[i]], 1); }
}
__global__ void prep_kernel(int n) {
    int i = blockIdx.x * blockDim.x + threadIdx.x;
    if (i < n) {
        int d = g_indeg[i];
        g_hp[i] = d > 0 ? 1.f : 0.f;
        g_invdeg[i] = 1.f / (float)(d > 0 ? d : 1);
    }
}
__global__ void scan1_kernel(int n) {
    __shared__ int sm[1024];
    int t = threadIdx.x;
    int i = blockIdx.x * 1024 + t;
    int v = (i < n) ? g_indeg[i] : 0;
    sm[t] = v;
    __syncthreads();
    for (int off = 1; off < 1024; off <<= 1) {
        int x = (t >= off) ? sm[t - off] : 0;
        __syncthreads();
        sm[t] += x;
        __syncthreads();
    }
    if (i < n) g_off[i] = sm[t] - v;
    if (t == 1023) g_bsum[blockIdx.x] = sm[1023];
}
__global__ void scan2_kernel(int nb) {
    if (threadIdx.x == 0) {
        int c = 0;
        for (int i = 0; i < nb; i++) { int x = g_bsum[i]; g_bsum[i] = c; c += x; }
    }
}
__global__ void scan3_kernel(int n) {
    int i = blockIdx.x * blockDim.x + threadIdx.x;
    if (i < n) g_off[i] += g_bsum[i >> 10];
}
__global__ void fill_kernel(const int* __restrict__ src, const int* __restrict__ dst, int e) {
    int i = blockIdx.x * blockDim.x + threadIdx.x;
    if (i < e) {
        int d = dst[i];
        int p = g_off[d] + atomicAdd(&g_cursor[d], 1);
        g_csr[p] = src[i];
    }
}

// ---------------- neighbor mean (half in, half out, fp32 accumulate) ----------------
__global__ void neigh_kernel(const uint32_t* __restrict__ Hh, uint32_t* __restrict__ Ngh, int n) {
    int gw = (blockIdx.x * blockDim.x + threadIdx.x) >> 5;
    int lane = threadIdx.x & 31;
    if (gw >= n) return;
    int start = g_off[gw];
    int deg = g_indeg[gw];
    const uint2* H2 = (const uint2*)Hh;
    float4 acc = make_float4(0.f, 0.f, 0.f, 0.f);
    for (int base = 0; base < deg; base += 32) {
        int e = base + lane;
        int s = (e < deg) ? g_csr[start + e] : 0;
        int cnt = min(32, deg - base);
        for (int j = 0; j < cnt; j++) {
            int sj = __shfl_sync(0xffffffffu, s, j);
            uint2 v = H2[(size_t)sj * 32 + lane];
            float2 f0 = h2f2(v.x), f1 = h2f2(v.y);
            acc.x += f0.x; acc.y += f0.y; acc.z += f1.x; acc.w += f1.y;
        }
    }
    float iv = g_invdeg[gw];
    uint2 o;
    o.x = f2h2(acc.x * iv, acc.y * iv);
    o.y = f2h2(acc.z * iv, acc.w * iv);
    ((uint2*)Ngh)[(size_t)gw * 32 + lane] = o;
}

// ---------------- pooling ----------------
__global__ void pool2_kernel(const float* __restrict__ Hin, int n) {
    __shared__ float sb[8 * 128];
    __shared__ float se[8];
    int tid = threadIdx.x, w = tid >> 5, lane = tid & 31;
    int gw = (blockIdx.x * blockDim.x + tid) >> 5;
    int nw = (gridDim.x * blockDim.x) >> 5;
    float mx = decf(g_maxbits);
    const float4* H4 = (const float4*)Hin;
    float4 acc = make_float4(0.f, 0.f, 0.f, 0.f);
    float es = 0.f;
    for (int i = gw; i < n; i += nw) {
        float s = g_scores[i];
        if (s >= -1e30f) {
            float e = expf(s - mx);
            if (lane == 0) es += e;
            float4 hv = H4[(size_t)i * 32 + lane];
            acc.x += e * hv.x; acc.y += e * hv.y; acc.z += e * hv.z; acc.w += e * hv.w;
        }
    }
    *(float4*)&sb[w * 128 + lane * 4] = acc;
    if (lane == 0) se[w] = es;
    __syncthreads();
    if (tid < 128) {
        float t = 0.f;
#pragma unroll
        for (int j = 0; j < 8; j++) t += sb[j * 128 + tid];
        if (t != 0.f) atomicAdd(&g_emb[tid], t);
    }
    if (tid == 0) {
        float t = 0.f;
#pragma unroll
        for (int j = 0; j < 8; j++) t += se[j];
        if (t != 0.f) atomicAdd(&g_sumexp, t);
    }
}
__global__ void finish_kernel(float* __restrict__ gout) {
    int t = threadIdx.x;
    gout[t] = g_emb[t] / g_sumexp;
}

// ---------------- launch ----------------
extern "C" void kernel_launch(void* const* d_in, const int* in_sizes, int n_in,
                              void* d_out, int out_size)
{
    const float* node_feats = (const float*)d_in[0];
    const int*   src        = (const int*)d_in[1];
    const int*   dst        = (const int*)d_in[2];
    const float* W_in       = (const float*)d_in[3];
    const float* b_in       = (const float*)d_in[4];
    const float* Ws         = (const float*)d_in[5];
    const float* bs         = (const float*)d_in[6];
    const float* Wn         = (const float*)d_in[7];
    const float* bn         = (const float*)d_in[8];
    const float* Wg         = (const float*)d_in[9];
    const float* bg         = (const float*)d_in[10];
    const float* gamma      = (const float*)d_in[11];
    const float* beta       = (const float*)d_in[12];
    const float* W_att      = (const float*)d_in[13];
    const float* b_att      = (const float*)d_in[14];
    const float* W_score    = (const float*)d_in[15];
    const float* b_score    = (const float*)d_in[16];

    int n = in_sizes[0] / H;
    int e = in_sizes[1];
    int L = in_sizes[6] / H;

    float* out_h = (float*)d_out;
    float* out_g = out_h + (size_t)n * H;

    float *hA, *hp;
    uint32_t *hAh, *hBh, *ngh;
    uint4* Wh;
    cudaGetSymbolAddress((void**)&hA, g_hA);
    cudaGetSymbolAddress((void**)&hAh, g_hAh);
    cudaGetSymbolAddress((void**)&hBh, g_hBh);
    cudaGetSymbolAddress((void**)&ngh, g_ngh);
    cudaGetSymbolAddress((void**)&hp, g_hp);
    cudaGetSymbolAddress((void**)&Wh, g_Wh4);

    cudaFuncSetAttribute(tc_gemm,  cudaFuncAttributeMaxDynamicSharedMemorySize, GSMEM_BYTES);
    cudaFuncSetAttribute(tc_score, cudaFuncAttributeMaxDynamicSharedMemorySize, SSMEM_BYTES);
    cudaFuncSetAttribute(tc_layer, cudaFuncAttributeMaxDynamicSharedMemorySize, LSMEM_BYTES);

    int nbN = (n + 255) / 256;
    int nbE = (e + 255) / 256;
    int nbT = (n + 127) / 128;
    int nbW = (n + 7) / 8;
    int nbS = (n + 1023) / 1024;
    int wtotal = (4 * L + 2) * 8192;

    // launch order keeps tc_gemm 4th (ncu capture slot)
    wconv_kernel<<<(wtotal + 255) / 256, 256>>>(W_in, Ws, Wn, Wg, W_att, L);
    zero_kernel<<<nbN, 256>>>(n);
    deg_kernel<<<nbE, 256>>>(src, dst, e);
    tc_gemm<<<nbT, 512, GSMEM_BYTES>>>(node_feats, Wh, b_in, hA, hAh, n);
    prep_kernel<<<nbN, 256>>>(n);
    scan1_kernel<<<nbS, 1024>>>(n);
    scan2_kernel<<<1, 32>>>(nbS);
    scan3_kernel<<<nbN, 256>>>(n);
    fill_kernel<<<nbE, 256>>>(src, dst, e);

    uint32_t* curh = hAh;
    uint32_t* otherh = hBh;
    for (int i = 0; i < L; i++) {
        const uint4* Wsp  = Wh + (size_t)(1 + i) * 2048;
        const uint4* Wnp  = Wh + (size_t)(1 + L + i) * 2048;
        const uint4* WgAp = Wh + (size_t)(1 + 2 * L + i) * 2048;
        const uint4* WgBp = Wh + (size_t)(1 + 3 * L + i) * 2048;
        const float* bs_i = bs + (size_t)i * H;
        const float* bn_i = bn + (size_t)i * H;
        const float* bg_i = bg + (size_t)i * H;
        const float* ga_i = gamma + (size_t)i * H;
        const float* be_i = beta + (size_t)i * H;

        neigh_kernel<<<nbW, 256>>>(curh, ngh, n);
        int last = (i == L - 1);
        tc_layer<<<148, 512, LSMEM_BYTES>>>(curh, ngh, Wsp, Wnp, WgAp, WgBp,
                                            bs_i, bn_i, bg_i, hp, ga_i, be_i,
                                            out_h, otherh, n, nbT, last);
        uint32_t* th = curh; curh = otherh; otherh = th;
    }

    tc_score<<<nbT, 512, SSMEM_BYTES>>>(curh, Wh + (size_t)(4 * L + 1) * 2048,
                                        b_att, W_score, b_score, n);
    pool2_kernel<<<64, 256>>>(out_h, n);
    finish_kernel<<<1, 128>>>(out_g);
}

// round 15
// speedup vs baseline: 1.3760x; 1.0428x over previous
#include <cuda_runtime.h>
#include <cuda_fp16.h>
#include <math.h>
#include <stdint.h>

#define MAXN 100000
#define MAXE 800000
#define H 128
#define NPAD (MAXN + 128)

// ---------------- device scratch ----------------
__device__ float g_hA[(size_t)MAXN * H];
__device__ uint32_t g_hAh[(size_t)NPAD * 64];   // half2 k-pair mirrors
__device__ uint32_t g_hBh[(size_t)NPAD * 64];
__device__ uint32_t g_ngh[(size_t)NPAD * 64];
__device__ uint4 g_Wh4[16 * 2048];              // preconverted weight panels (half2 kpair)
__device__ int   g_indeg[MAXN];
__device__ int   g_outdeg[MAXN];
__device__ int   g_cursor[MAXN];
__device__ int   g_off[MAXN];
__device__ int   g_csr[MAXE];
__device__ int   g_bsum[128];
__device__ float g_hp[MAXN];
__device__ float g_invdeg[MAXN];
__device__ float g_scores[MAXN];
__device__ float g_emb[H];
__device__ float g_sumexp;
__device__ unsigned g_maxbits;

__device__ __forceinline__ float neg_inf() { return __int_as_float(0xff800000); }
__device__ __forceinline__ unsigned encf(float f) {
    unsigned u = __float_as_uint(f);
    return (u & 0x80000000u) ? ~u : (u | 0x80000000u);
}
__device__ __forceinline__ float decf(unsigned u) {
    return (u & 0x80000000u) ? __uint_as_float(u ^ 0x80000000u) : __uint_as_float(~u);
}

// ---------------- fp16 + fast-math helpers ----------------
__device__ __forceinline__ uint32_t f2h2(float a, float b) {
    __half2 h = __floats2half2_rn(a, b);
    return *(uint32_t*)&h;
}
__device__ __forceinline__ float2 h2f2(uint32_t u) {
    __half2 h = *(__half2*)&u;
    return __half22float2(h);
}
__device__ __forceinline__ float sigmoid_fast(float x) {
    return __fdividef(1.f, 1.f + __expf(-x));
}
__device__ __forceinline__ float tanh_approx(float x) {
    float r;
    asm("tanh.approx.f32 %0, %1;" : "=f"(r) : "f"(x));
    return r;
}
__device__ __forceinline__ void mma16816(float* c, uint32_t a0, uint32_t a1, uint32_t a2, uint32_t a3,
                                         uint32_t b0, uint32_t b1) {
    asm volatile("mma.sync.aligned.m16n8k16.row.col.f32.f16.f16.f32 "
                 "{%0,%1,%2,%3}, {%4,%5,%6,%7}, {%8,%9}, {%0,%1,%2,%3};"
                 : "+f"(c[0]), "+f"(c[1]), "+f"(c[2]), "+f"(c[3])
                 : "r"(a0), "r"(a1), "r"(a2), "r"(a3), "r"(b0), "r"(b1));
}
__device__ __forceinline__ uint32_t smem_u32(const void* p) {
    uint32_t a;
    asm("{ .reg .u64 t; cvta.to.shared.u64 t, %1; cvt.u32.u64 %0, t; }" : "=r"(a) : "l"(p));
    return a;
}
#define CP_COMMIT() asm volatile("cp.async.commit_group;" ::: "memory")
#define CP_WAIT0()  asm volatile("cp.async.wait_group 0;" ::: "memory")
#define PAIR_BAR(warpM) asm volatile("bar.sync %0, 64;" :: "r"(1 + (warpM)) : "memory")

// A tile: 128 rows x 64 half2, stride 68 u32.  W tile: 64 kp-rows x 128 half2, stride 136 u32.
#define AP_STRIDE 68
#define WP_STRIDE 136
#define SZ_AP (128 * AP_STRIDE)     // 8704 u32
#define SZ_WP (64 * WP_STRIDE)      // 8704 u32
#define GSMEM_BYTES ((SZ_AP + SZ_WP + 128) * 4)
#define SSMEM_BYTES ((SZ_AP + SZ_WP + 512) * 4)
// tc_layer (multi-tile): Acur | Am | W0..W3 | consts | lnbuf
#define L_OFF_AM   SZ_AP
#define L_OFF_W0   (2 * SZ_AP)
#define L_OFF_SC   (2 * SZ_AP + 4 * SZ_WP)
#define LSMEM_BYTES ((2 * SZ_AP + 4 * SZ_WP + 640 + 512) * 4)

// ---------------- tile loaders (512-thread CTAs) ----------------
__device__ __forceinline__ void load_a_f32(const float4* __restrict__ G, int r0, int n, uint32_t* sm) {
    int t = threadIdx.x;
#pragma unroll
    for (int i = 0; i < 8; i++) {
        int g = t + i * 512;
        int row = g >> 5, c4 = g & 31;
        float4 v = make_float4(0.f, 0.f, 0.f, 0.f);
        if (r0 + row < n) v = G[(size_t)(r0 + row) * 32 + c4];
        uint2 w;
        w.x = f2h2(v.x, v.y);
        w.y = f2h2(v.z, v.w);
        *(uint2*)(sm + row * AP_STRIDE + c4 * 2) = w;
    }
}
__device__ __forceinline__ void copy_a_async(const uint32_t* __restrict__ src, int r0, int n, uint32_t dstb) {
    int t = threadIdx.x;
#pragma unroll
    for (int i = 0; i < 4; i++) {
        int g = t + i * 512;
        int row = g >> 4, q = g & 15;
        uint32_t dst = dstb + (uint32_t)(row * AP_STRIDE + q * 4) * 4u;
        const uint32_t* s = src + (size_t)(r0 + row) * 64 + q * 4;
        int sz = (r0 + row < n) ? 16 : 0;
        asm volatile("cp.async.cg.shared.global [%0], [%1], 16, %2;" :: "r"(dst), "l"(s), "r"(sz));
    }
}
__device__ __forceinline__ void copy_w_async(const uint4* __restrict__ src, uint32_t dstb) {
    int t = threadIdx.x;
#pragma unroll
    for (int i = 0; i < 4; i++) {
        int g = t + i * 512;
        int kp = g >> 5, c4 = g & 31;
        uint32_t dst = dstb + (uint32_t)(kp * WP_STRIDE + c4 * 4) * 4u;
        asm volatile("cp.async.cg.shared.global [%0], [%1], 16;" :: "r"(dst), "l"(src + kp * 32 + c4));
    }
}

// warp-tile MMA: 16 warps, each 16 rows x 64 cols -> acc[8][4]
__device__ __forceinline__ void mma_tile(const uint32_t* AP, const uint32_t* WP,
                                         float acc[8][4], int rb, int warpN,
                                         int gid, int tq) {
#pragma unroll
    for (int ks = 0; ks < 8; ks++) {
        int kp0 = ks * 8;
        uint32_t a0 = AP[(rb + gid) * AP_STRIDE + kp0 + tq];
        uint32_t a1 = AP[(rb + gid + 8) * AP_STRIDE + kp0 + tq];
        uint32_t a2 = AP[(rb + gid) * AP_STRIDE + kp0 + tq + 4];
        uint32_t a3 = AP[(rb + gid + 8) * AP_STRIDE + kp0 + tq + 4];
#pragma unroll
        for (int nt = 0; nt < 8; nt++) {
            int cb = warpN * 64 + nt * 8 + gid;
            uint32_t b0 = WP[(kp0 + tq) * WP_STRIDE + cb];
            uint32_t b1 = WP[(kp0 + tq + 4) * WP_STRIDE + cb];
            mma16816(acc[nt], a0, a1, a2, a3, b0, b1);
        }
    }
}

// dual-pass MMA: shared A fragments feed two weight panels (acc1 += A@W1, acc2 += A@W2)
__device__ __forceinline__ void mma_tile2(const uint32_t* AP, const uint32_t* W1, const uint32_t* W2,
                                          float acc1[8][4], float acc2[8][4], int rb, int warpN,
                                          int gid, int tq) {
#pragma unroll
    for (int ks = 0; ks < 8; ks++) {
        int kp0 = ks * 8;
        uint32_t a0 = AP[(rb + gid) * AP_STRIDE + kp0 + tq];
        uint32_t a1 = AP[(rb + gid + 8) * AP_STRIDE + kp0 + tq];
        uint32_t a2 = AP[(rb + gid) * AP_STRIDE + kp0 + tq + 4];
        uint32_t a3 = AP[(rb + gid + 8) * AP_STRIDE + kp0 + tq + 4];
#pragma unroll
        for (int nt = 0; nt < 8; nt++) {
            int cb = warpN * 64 + nt * 8 + gid;
            uint32_t b0 = W1[(kp0 + tq) * WP_STRIDE + cb];
            uint32_t b1 = W1[(kp0 + tq + 4) * WP_STRIDE + cb];
            mma16816(acc1[nt], a0, a1, a2, a3, b0, b1);
            uint32_t c0 = W2[(kp0 + tq) * WP_STRIDE + cb];
            uint32_t c1 = W2[(kp0 + tq + 4) * WP_STRIDE + cb];
            mma16816(acc2[nt], a0, a1, a2, a3, c0, c1);
        }
    }
}

// ---------------- weight preconversion ----------------
__global__ void wconv_kernel(const float* __restrict__ W_in, const float* __restrict__ Ws,
                             const float* __restrict__ Wn, const float* __restrict__ Wg,
                             const float* __restrict__ W_att, int L) {
    int idx = blockIdx.x * blockDim.x + threadIdx.x;
    int total = (4 * L + 2) * 8192;
    if (idx >= total) return;
    int p = idx >> 13;
    int j = idx & 8191;
    int kp = j >> 7, nn = j & 127;
    const float* src;
    if (p == 0) src = W_in;
    else if (p <= L) src = Ws + (size_t)(p - 1) * H * H;
    else if (p <= 2 * L) src = Wn + (size_t)(p - 1 - L) * H * H;
    else if (p <= 3 * L) src = Wg + (size_t)(p - 1 - 2 * L) * 2 * H * H;
    else if (p <= 4 * L) src = Wg + (size_t)(p - 1 - 3 * L) * 2 * H * H + (size_t)H * H;
    else src = W_att;
    ((uint32_t*)g_Wh4)[idx] = f2h2(src[(size_t)(2 * kp) * H + nn], src[(size_t)(2 * kp + 1) * H + nn]);
}

// ---------------- GEMM (input projection): C = A@W + bias, + half mirror ----------------
__global__ __launch_bounds__(512) void tc_gemm(
    const float* __restrict__ A, const uint4* __restrict__ Wp,
    const float* __restrict__ bias, float* __restrict__ C, uint32_t* __restrict__ Ch, int n)
{
    extern __shared__ uint32_t smem[];
    uint32_t* AP = smem;
    uint32_t* WP = smem + SZ_AP;
    float* sb = (float*)(smem + SZ_AP + SZ_WP);
    uint32_t sbase = smem_u32(smem);

    int tid = threadIdx.x, wid = tid >> 5, lane = tid & 31;
    int warpM = wid >> 1, warpN = wid & 1, gid = lane >> 2, tq = lane & 3;
    int r0 = blockIdx.x * 128;
    int rb = warpM * 16;

    copy_w_async(Wp, sbase + SZ_AP * 4);
    CP_COMMIT();
    load_a_f32((const float4*)A, r0, n, AP);
    if (tid < 128) sb[tid] = bias[tid];
    CP_WAIT0();
    __syncthreads();

    float acc[8][4];
#pragma unroll
    for (int nt = 0; nt < 8; nt++)
#pragma unroll
        for (int j = 0; j < 4; j++) acc[nt][j] = 0.f;

    mma_tile(AP, WP, acc, rb, warpN, gid, tq);

#pragma unroll
    for (int p = 0; p < 2; p++) {
        int row = r0 + rb + p * 8 + gid;
        if (row >= n) continue;
#pragma unroll
        for (int nt = 0; nt < 8; nt++) {
            int cb = warpN * 64 + nt * 8 + 2 * tq;
            float2 o;
            o.x = acc[nt][2 * p + 0] + sb[cb];
            o.y = acc[nt][2 * p + 1] + sb[cb + 1];
            *(float2*)(C + (size_t)row * H + cb) = o;
            Ch[(size_t)row * 64 + (cb >> 1)] = f2h2(o.x, o.y);
        }
    }
}

// ---------------- multi-tile fused layer kernel (all 4 W panels resident) ----------------
__global__ __launch_bounds__(512) void tc_layer(
    const uint32_t* __restrict__ curh, const uint32_t* __restrict__ ngh,
    const uint4* __restrict__ Wsp, const uint4* __restrict__ Wnp,
    const uint4* __restrict__ WgAp, const uint4* __restrict__ WgBp,
    const float* __restrict__ bs, const float* __restrict__ bn, const float* __restrict__ bg,
    const float* __restrict__ coef,
    const float* __restrict__ gamma, const float* __restrict__ beta,
    float* __restrict__ Houtf, uint32_t* __restrict__ Houth, int n, int nTiles, int writef)
{
    extern __shared__ uint32_t smem[];
    uint32_t* Acur = smem;
    uint32_t* Am   = smem + L_OFF_AM;          // neigh tile, later m tile
    uint32_t* W0   = smem + L_OFF_W0;          // Ws | Wn | WgA | WgB resident
    float* sc  = (float*)(smem + L_OFF_SC);    // bs|bn|bg|gamma|beta
    float* lnb = sc + 640;
    uint32_t sbase = smem_u32(smem);

    int tid = threadIdx.x, wid = tid >> 5, lane = tid & 31;
    int warpM = wid >> 1, warpN = wid & 1, gid = lane >> 2, tq = lane & 3;
    int rb = warpM * 16;

    int t0 = blockIdx.x;
    if (t0 < nTiles) {
        copy_a_async(curh, t0 * 128, n, sbase);
        copy_a_async(ngh, t0 * 128, n, sbase + L_OFF_AM * 4);
    }
    copy_w_async(Wsp,  sbase + L_OFF_W0 * 4);
    copy_w_async(Wnp,  sbase + (L_OFF_W0 + SZ_WP) * 4);
    copy_w_async(WgAp, sbase + (L_OFF_W0 + 2 * SZ_WP) * 4);
    copy_w_async(WgBp, sbase + (L_OFF_W0 + 3 * SZ_WP) * 4);
    CP_COMMIT();
    if (tid < 128) {
        sc[tid] = bs[tid]; sc[128 + tid] = bn[tid]; sc[256 + tid] = bg[tid];
        sc[384 + tid] = gamma[tid]; sc[512 + tid] = beta[tid];
    }
    CP_WAIT0();
    __syncthreads();

    for (int tile = t0; tile < nTiles; tile += gridDim.x) {
        int r0 = tile * 128;

        float acc1[8][4], acc2[8][4];
#pragma unroll
        for (int nt = 0; nt < 8; nt++)
#pragma unroll
            for (int j = 0; j < 4; j++) { acc1[nt][j] = 0.f; acc2[nt][j] = 0.f; }

        // merged passes 1&3: one A-fragment stream feeds Ws->acc1 and WgA->acc2
        mma_tile2(Acur, W0, W0 + 2 * SZ_WP, acc1, acc2, rb, warpN, gid, tq);
        // pass 2: neigh @ Wn -> acc1  (reads only this warp's 16 rows of Am)
        mma_tile(Am, W0 + SZ_WP, acc1, rb, warpN, gid, tq);
        PAIR_BAR(warpM);   // pair-scope: partner finished reading Am rows rb..rb+15

        // m = acc1 + bs + cf*bn (exact fp32 in regs); write half m over Am
#pragma unroll
        for (int p = 0; p < 2; p++) {
            int lrow = rb + p * 8 + gid;
            int row = r0 + lrow;
            if (row >= n) continue;
            float cf = coef[row];
#pragma unroll
            for (int nt = 0; nt < 8; nt++) {
                int cb = warpN * 64 + nt * 8 + 2 * tq;
                float v0 = acc1[nt][2 * p + 0] + sc[cb + 0] + cf * sc[128 + cb + 0];
                float v1 = acc1[nt][2 * p + 1] + sc[cb + 1] + cf * sc[128 + cb + 1];
                acc1[nt][2 * p + 0] = v0;
                acc1[nt][2 * p + 1] = v1;
                Am[lrow * AP_STRIDE + (cb >> 1)] = f2h2(v0, v1);
            }
        }
        PAIR_BAR(warpM);   // pair-scope: both column halves of m rows rb..rb+15 visible
        mma_tile(Am, W0 + 3 * SZ_WP, acc2, rb, warpN, gid, tq);   // += m@WgB

        // epilogue: gate (fast sigmoid) + blend (h from half mirror) + LN + ReLU
        float rsum[2] = {0.f, 0.f};
        float rsq[2] = {0.f, 0.f};
#pragma unroll
        for (int p = 0; p < 2; p++) {
            int lrow = rb + p * 8 + gid;
            int row = r0 + lrow;
            if (row >= n) continue;
#pragma unroll
            for (int nt = 0; nt < 8; nt++) {
                int cb = warpN * 64 + nt * 8 + 2 * tq;
                float2 hv = h2f2(Acur[lrow * AP_STRIDE + (cb >> 1)]);
                float g, v;
                g = sigmoid_fast(acc2[nt][2 * p + 0] + sc[256 + cb]);
                v = g * acc1[nt][2 * p + 0] + (1.f - g) * hv.x;
                acc1[nt][2 * p + 0] = v; rsum[p] += v; rsq[p] += v * v;
                g = sigmoid_fast(acc2[nt][2 * p + 1] + sc[256 + cb + 1]);
                v = g * acc1[nt][2 * p + 1] + (1.f - g) * hv.y;
                acc1[nt][2 * p + 1] = v; rsum[p] += v; rsq[p] += v * v;
            }
        }
#pragma unroll
        for (int p = 0; p < 2; p++) {
            rsum[p] += __shfl_xor_sync(0xffffffffu, rsum[p], 1);
            rsum[p] += __shfl_xor_sync(0xffffffffu, rsum[p], 2);
            rsq[p] += __shfl_xor_sync(0xffffffffu, rsq[p], 1);
            rsq[p] += __shfl_xor_sync(0xffffffffu, rsq[p], 2);
        }
        if (tq == 0) {
#pragma unroll
            for (int p = 0; p < 2; p++) {
                int lrow = rb + p * 8 + gid;
                lnb[lrow * 4 + warpN * 2 + 0] = rsum[p];
                lnb[lrow * 4 + warpN * 2 + 1] = rsq[p];
            }
        }
        __syncthreads();   // full: lnb visible; ALL Acur/Am reads complete

        // prefetch next tile's A pair (overlaps LN-store loop; Acur/Am no longer read)
        int tnext = tile + gridDim.x;
        if (tnext < nTiles) {
            copy_a_async(curh, tnext * 128, n, sbase);
            copy_a_async(ngh, tnext * 128, n, sbase + L_OFF_AM * 4);
            CP_COMMIT();
        }

#pragma unroll
        for (int p = 0; p < 2; p++) {
            int lrow = rb + p * 8 + gid;
            int row = r0 + lrow;
            if (row >= n) continue;
            float sum = lnb[lrow * 4 + 0] + lnb[lrow * 4 + 2];
            float sq  = lnb[lrow * 4 + 1] + lnb[lrow * 4 + 3];
            float mu = sum * (1.f / 128.f);
            float var = sq * (1.f / 128.f) - mu * mu;
            float rs = rsqrtf(var + 1e-5f);
            float* orow = Houtf + (size_t)row * H;
#pragma unroll
            for (int nt = 0; nt < 8; nt++) {
                int cb = warpN * 64 + nt * 8 + 2 * tq;
                float2 o;
                o.x = fmaxf(fmaf((acc1[nt][2 * p + 0] - mu) * rs, sc[384 + cb], sc[512 + cb]), 0.f);
                o.y = fmaxf(fmaf((acc1[nt][2 * p + 1] - mu) * rs, sc[384 + cb + 1], sc[512 + cb + 1]), 0.f);
                if (writef) *(float2*)(orow + cb) = o;
                Houth[(size_t)row * 64 + (cb >> 1)] = f2h2(o.x, o.y);
            }
        }
        if (tnext < nTiles) CP_WAIT0();
        __syncthreads();
    }
}

// ---------------- fused attention score ----------------
__global__ __launch_bounds__(512) void tc_score(
    const uint32_t* __restrict__ Ah, const uint4* __restrict__ Wp,
    const float* __restrict__ bias, const float* __restrict__ Wsc,
    const float* __restrict__ bsc, int n)
{
    extern __shared__ uint32_t smem[];
    uint32_t* AP = smem;
    uint32_t* WP = smem + SZ_AP;
    float* sb = (float*)(smem + SZ_AP + SZ_WP);
    float* sw = sb + 128;
    float* lnb = sw + 128;
    uint32_t sbase = smem_u32(smem);

    int tid = threadIdx.x, wid = tid >> 5, lane = tid & 31;
    int warpM = wid >> 1, warpN = wid & 1, gid = lane >> 2, tq = lane & 3;
    int r0 = blockIdx.x * 128;
    int rb = warpM * 16;

    copy_a_async(Ah, r0, n, sbase);
    copy_w_async(Wp, sbase + SZ_AP * 4);
    if (tid < 128) sb[tid] = bias[tid];
    else if (tid < 256) sw[tid - 128] = Wsc[tid - 128];
    CP_COMMIT(); CP_WAIT0();
    __syncthreads();

    float acc[8][4];
#pragma unroll
    for (int nt = 0; nt < 8; nt++)
#pragma unroll
        for (int j = 0; j < 4; j++) acc[nt][j] = 0.f;

    mma_tile(AP, WP, acc, rb, warpN, gid, tq);

    float part[2] = {0.f, 0.f};
#pragma unroll
    for (int nt = 0; nt < 8; nt++) {
        int cb = warpN * 64 + nt * 8 + 2 * tq;
#pragma unroll
        for (int p = 0; p < 2; p++) {
            part[p] += tanh_approx(acc[nt][2 * p + 0] + sb[cb]) * sw[cb];
            part[p] += tanh_approx(acc[nt][2 * p + 1] + sb[cb + 1]) * sw[cb + 1];
        }
    }
#pragma unroll
    for (int p = 0; p < 2; p++) {
        part[p] += __shfl_xor_sync(0xffffffffu, part[p], 1);
        part[p] += __shfl_xor_sync(0xffffffffu, part[p], 2);
    }
    if (tq == 0) {
#pragma unroll
        for (int p = 0; p < 2; p++) {
            int lrow = rb + p * 8 + gid;
            lnb[lrow * 2 + warpN] = part[p];
        }
    }
    __syncthreads();
    if (warpN == 0 && tq == 0) {
#pragma unroll
        for (int p = 0; p < 2; p++) {
            int lrow = rb + p * 8 + gid;
            int row = r0 + lrow;
            if (row >= n) continue;
            float scv = lnb[lrow * 2 + 0] + lnb[lrow * 2 + 1] + bsc[0];
            bool sink = (g_outdeg[row] == 0);
            g_scores[row] = sink ? scv : neg_inf();
            if (sink) atomicMax(&g_maxbits, encf(scv));
        }
    }
}

// ---------------- graph prep ----------------
__global__ void zero_kernel(int n) {
    int i = blockIdx.x * blockDim.x + threadIdx.x;
    if (i < n) { g_indeg[i] = 0; g_outdeg[i] = 0; g_cursor[i] = 0; }
    if (i < H) g_emb[i] = 0.f;
    if (i == 0) { g_maxbits = encf(neg_inf()); g_sumexp = 0.f; }
}
__global__ void deg_kernel(const int* __restrict__ src, const int* __restrict__ dst, int e) {
    int i = blockIdx.x * blockDim.x + threadIdx.x;
    if (i < e) { atomicAdd(&g_indeg[dst[i]], 1); atomicAdd(&g_outdeg[src[i]], 1); }
}
__global__ void prep_kernel(int n) {
    int i = blockIdx.x * blockDim.x + threadIdx.x;
    if (i < n) {
        int d = g_indeg[i];
        g_hp[i] = d > 0 ? 1.f : 0.f;
        g_invdeg[i] = 1.f / (float)(d > 0 ? d : 1);
    }
}
__global__ void scan1_kernel(int n) {
    __shared__ int sm[1024];
    int t = threadIdx.x;
    int i = blockIdx.x * 1024 + t;
    int v = (i < n) ? g_indeg[i] : 0;
    sm[t] = v;
    __syncthreads();
    for (int off = 1; off < 1024; off <<= 1) {
        int x = (t >= off) ? sm[t - off] : 0;
        __syncthreads();
        sm[t] += x;
        __syncthreads();
    }
    if (i < n) g_off[i] = sm[t] - v;
    if (t == 1023) g_bsum[blockIdx.x] = sm[1023];
}
__global__ void scan2_kernel(int nb) {
    if (threadIdx.x == 0) {
        int c = 0;
        for (int i = 0; i < nb; i++) { int x = g_bsum[i]; g_bsum[i] = c; c += x; }
    }
}
__global__ void scan3_kernel(int n) {
    int i = blockIdx.x * blockDim.x + threadIdx.x;
    if (i < n) g_off[i] += g_bsum[i >> 10];
}
__global__ void fill_kernel(const int* __restrict__ src, const int* __restrict__ dst, int e) {
    int i = blockIdx.x * blockDim.x + threadIdx.x;
    if (i < e) {
        int d = dst[i];
        int p = g_off[d] + atomicAdd(&g_cursor[d], 1);
        g_csr[p] = src[i];
    }
}

// ---------------- neighbor mean (half in, half out, fp32 accumulate) ----------------
__global__ void neigh_kernel(const uint32_t* __restrict__ Hh, uint32_t* __restrict__ Ngh, int n) {
    int gw = (blockIdx.x * blockDim.x + threadIdx.x) >> 5;
    int lane = threadIdx.x & 31;
    if (gw >= n) return;
    int start = g_off[gw];
    int deg = g_indeg[gw];
    const uint2* H2 = (const uint2*)Hh;
    float4 acc = make_float4(0.f, 0.f, 0.f, 0.f);
    for (int base = 0; base < deg; base += 32) {
        int e = base + lane;
        int s = (e < deg) ? g_csr[start + e] : 0;
        int cnt = min(32, deg - base);
        for (int j = 0; j < cnt; j++) {
            int sj = __shfl_sync(0xffffffffu, s, j);
            uint2 v = H2[(size_t)sj * 32 + lane];
            float2 f0 = h2f2(v.x), f1 = h2f2(v.y);
            acc.x += f0.x; acc.y += f0.y; acc.z += f1.x; acc.w += f1.y;
        }
    }
    float iv = g_invdeg[gw];
    uint2 o;
    o.x = f2h2(acc.x * iv, acc.y * iv);
    o.y = f2h2(acc.z * iv, acc.w * iv);
    ((uint2*)Ngh)[(size_t)gw * 32 + lane] = o;
}

// ---------------- pooling ----------------
__global__ void pool2_kernel(const float* __restrict__ Hin, int n) {
    __shared__ float sb[8 * 128];
    __shared__ float se[8];
    int tid = threadIdx.x, w = tid >> 5, lane = tid & 31;
    int gw = (blockIdx.x * blockDim.x + tid) >> 5;
    int nw = (gridDim.x * blockDim.x) >> 5;
    float mx = decf(g_maxbits);
    const float4* H4 = (const float4*)Hin;
    float4 acc = make_float4(0.f, 0.f, 0.f, 0.f);
    float es = 0.f;
    for (int i = gw; i < n; i += nw) {
        float s = g_scores[i];
        if (s >= -1e30f) {
            float e = __expf(s - mx);
            if (lane == 0) es += e;
            float4 hv = H4[(size_t)i * 32 + lane];
            acc.x += e * hv.x; acc.y += e * hv.y; acc.z += e * hv.z; acc.w += e * hv.w;
        }
    }
    *(float4*)&sb[w * 128 + lane * 4] = acc;
    if (lane == 0) se[w] = es;
    __syncthreads();
    if (tid < 128) {
        float t = 0.f;
#pragma unroll
        for (int j = 0; j < 8; j++) t += sb[j * 128 + tid];
        if (t != 0.f) atomicAdd(&g_emb[tid], t);
    }
    if (tid == 0) {
        float t = 0.f;
#pragma unroll
        for (int j = 0; j < 8; j++) t += se[j];
        if (t != 0.f) atomicAdd(&g_sumexp, t);
    }
}
__global__ void finish_kernel(float* __restrict__ gout) {
    int t = threadIdx.x;
    gout[t] = g_emb[t] / g_sumexp;
}

// ---------------- launch ----------------
extern "C" void kernel_launch(void* const* d_in, const int* in_sizes, int n_in,
                              void* d_out, int out_size)
{
    const float* node_feats = (const float*)d_in[0];
    const int*   src        = (const int*)d_in[1];
    const int*   dst        = (const int*)d_in[2];
    const float* W_in       = (const float*)d_in[3];
    const float* b_in       = (const float*)d_in[4];
    const float* Ws         = (const float*)d_in[5];
    const float* bs         = (const float*)d_in[6];
    const float* Wn         = (const float*)d_in[7];
    const float* bn         = (const float*)d_in[8];
    const float* Wg         = (const float*)d_in[9];
    const float* bg         = (const float*)d_in[10];
    const float* gamma      = (const float*)d_in[11];
    const float* beta       = (const float*)d_in[12];
    const float* W_att      = (const float*)d_in[13];
    const float* b_att      = (const float*)d_in[14];
    const float* W_score    = (const float*)d_in[15];
    const float* b_score    = (const float*)d_in[16];

    int n = in_sizes[0] / H;
    int e = in_sizes[1];
    int L = in_sizes[6] / H;

    float* out_h = (float*)d_out;
    float* out_g = out_h + (size_t)n * H;

    float *hA, *hp;
    uint32_t *hAh, *hBh, *ngh;
    uint4* Wh;
    cudaGetSymbolAddress((void**)&hA, g_hA);
    cudaGetSymbolAddress((void**)&hAh, g_hAh);
    cudaGetSymbolAddress((void**)&hBh, g_hBh);
    cudaGetSymbolAddress((void**)&ngh, g_ngh);
    cudaGetSymbolAddress((void**)&hp, g_hp);
    cudaGetSymbolAddress((void**)&Wh, g_Wh4);

    cudaFuncSetAttribute(tc_gemm,  cudaFuncAttributeMaxDynamicSharedMemorySize, GSMEM_BYTES);
    cudaFuncSetAttribute(tc_score, cudaFuncAttributeMaxDynamicSharedMemorySize, SSMEM_BYTES);
    cudaFuncSetAttribute(tc_layer, cudaFuncAttributeMaxDynamicSharedMemorySize, LSMEM_BYTES);

    int nbN = (n + 255) / 256;
    int nbE = (e + 255) / 256;
    int nbT = (n + 127) / 128;
    int nbW = (n + 7) / 8;
    int nbS = (n + 1023) / 1024;
    int wtotal = (4 * L + 2) * 8192;

    // launch order keeps tc_gemm 4th (ncu capture slot)
    wconv_kernel<<<(wtotal + 255) / 256, 256>>>(W_in, Ws, Wn, Wg, W_att, L);
    zero_kernel<<<nbN, 256>>>(n);
    deg_kernel<<<nbE, 256>>>(src, dst, e);
    tc_gemm<<<nbT, 512, GSMEM_BYTES>>>(node_feats, Wh, b_in, hA, hAh, n);
    prep_kernel<<<nbN, 256>>>(n);
    scan1_kernel<<<nbS, 1024>>>(n);
    scan2_kernel<<<1, 32>>>(nbS);
    scan3_kernel<<<nbN, 256>>>(n);
    fill_kernel<<<nbE, 256>>>(src, dst, e);

    uint32_t* curh = hAh;
    uint32_t* otherh = hBh;
    for (int i = 0; i < L; i++) {
        const uint4* Wsp  = Wh + (size_t)(1 + i) * 2048;
        const uint4* Wnp  = Wh + (size_t)(1 + L + i) * 2048;
        const uint4* WgAp = Wh + (size_t)(1 + 2 * L + i) * 2048;
        const uint4* WgBp = Wh + (size_t)(1 + 3 * L + i) * 2048;
        const float* bs_i = bs + (size_t)i * H;
        const float* bn_i = bn + (size_t)i * H;
        const float* bg_i = bg + (size_t)i * H;
        const float* ga_i = gamma + (size_t)i * H;
        const float* be_i = beta + (size_t)i * H;

        neigh_kernel<<<nbW, 256>>>(curh, ngh, n);
        int last = (i == L - 1);
        tc_layer<<<148, 512, LSMEM_BYTES>>>(curh, ngh, Wsp, Wnp, WgAp, WgBp,
                                            bs_i, bn_i, bg_i, hp, ga_i, be_i,
                                            out_h, otherh, n, nbT, last);
        uint32_t* th = curh; curh = otherh; otherh = th;
    }

    tc_score<<<nbT, 512, SSMEM_BYTES>>>(curh, Wh + (size_t)(4 * L + 1) * 2048,
                                        b_att, W_score, b_score, n);
    pool2_kernel<<<64, 256>>>(out_h, n);
    finish_kernel<<<1, 128>>>(out_g);
}